// round 2
// baseline (speedup 1.0000x reference)
#include <cuda_runtime.h>
#include <math.h>

// Problem dims
#define R_ROWS   1024      // B*E = 16*64
#define LATENT   128
#define N_ATOMS  1024
#define N_FRAMES 128
#define SAMPLES  32768
#define WIN      512
#define HOP      256

// Scratch (static device globals — no runtime allocation allowed)
__device__ float g_sel[R_ROWS * N_ATOMS];      // softmax weights   (4 MB)
__device__ float g_res[R_ROWS * SAMPLES];      // mixed audio       (128 MB)
__device__ float g_mom[R_ROWS * N_FRAMES];     // cumprod momentum  (0.5 MB)
__device__ float g_scale[R_ROWS * N_FRAMES];   // mom/(norm+eps)    (0.5 MB)
__device__ float g_hann[WIN];

// ---------------------------------------------------------------------------
// K0: hann window table (periodic)
// ---------------------------------------------------------------------------
__global__ void k_hann() {
    int w = threadIdx.x;
    if (w < WIN)
        g_hann[w] = 0.5f * (1.0f - cosf((float)(2.0 * 3.14159265358979323846 / (double)WIN) * (float)w));
}

// ---------------------------------------------------------------------------
// K1: per-row selection softmax + momentum cumprod. One block per row.
// ---------------------------------------------------------------------------
__global__ __launch_bounds__(256) void k_sel_mom(
    const float* __restrict__ x,
    const float* __restrict__ W_sel, const float* __restrict__ b_sel,
    const float* __restrict__ W_mom, const float* __restrict__ b_mom,
    float* __restrict__ out_mom, int write_mom)
{
    __shared__ float xs[LATENT];
    __shared__ float red[256];
    __shared__ float lm[N_FRAMES];

    const int r   = blockIdx.x;
    const int tid = threadIdx.x;

    if (tid < LATENT) xs[tid] = x[r * LATENT + tid];
    __syncthreads();

    // --- selection logits: 4 atoms per thread (a = tid + 256*i) ---
    float z[4];
    #pragma unroll
    for (int i = 0; i < 4; i++) {
        const int a = tid + 256 * i;
        const float4* wp = (const float4*)(W_sel + a * LATENT);
        float acc = 0.f;
        #pragma unroll
        for (int l4 = 0; l4 < LATENT / 4; l4++) {
            float4 w4 = wp[l4];
            acc += xs[l4 * 4 + 0] * w4.x + xs[l4 * 4 + 1] * w4.y
                 + xs[l4 * 4 + 2] * w4.z + xs[l4 * 4 + 3] * w4.w;
        }
        z[i] = acc + b_sel[a];
    }

    // block max
    float m = fmaxf(fmaxf(z[0], z[1]), fmaxf(z[2], z[3]));
    red[tid] = m;
    __syncthreads();
    for (int s = 128; s > 0; s >>= 1) {
        if (tid < s) red[tid] = fmaxf(red[tid], red[tid + s]);
        __syncthreads();
    }
    m = red[0];
    __syncthreads();

    // exp + block sum
    float e[4], psum = 0.f;
    #pragma unroll
    for (int i = 0; i < 4; i++) { e[i] = expf(z[i] - m); psum += e[i]; }
    red[tid] = psum;
    __syncthreads();
    for (int s = 128; s > 0; s >>= 1) {
        if (tid < s) red[tid] += red[tid + s];
        __syncthreads();
    }
    const float inv = 1.0f / red[0];
    #pragma unroll
    for (int i = 0; i < 4; i++)
        g_sel[r * N_ATOMS + tid + 256 * i] = e[i] * inv;

    // --- momentum: 128 frame logits, then serial log-cumsum ---
    if (tid < N_FRAMES) {
        const float4* wp = (const float4*)(W_mom + tid * LATENT);
        float acc = 0.f;
        #pragma unroll
        for (int l4 = 0; l4 < LATENT / 4; l4++) {
            float4 w4 = wp[l4];
            acc += xs[l4 * 4 + 0] * w4.x + xs[l4 * 4 + 1] * w4.y
                 + xs[l4 * 4 + 2] * w4.z + xs[l4 * 4 + 3] * w4.w;
        }
        acc += b_mom[tid];
        const float sg = 1.0f / (1.0f + expf(-acc));
        lm[tid] = logf(1e-12f + 0.2f + 0.72f * sg);  // RES_FACTOR = 0.8*0.9
    }
    __syncthreads();
    if (tid == 0) {
        float c = 0.f;
        for (int f = 0; f < N_FRAMES; f++) {
            c += lm[f];
            const float mm = expf(c);
            g_mom[r * N_FRAMES + f] = mm;
            if (write_mom) out_mom[r * N_FRAMES + f] = mm;
        }
    }
}

// ---------------------------------------------------------------------------
// K2: res = sel @ atoms   (M=1024, N=32768, K=1024)   128x128 tile, BK=8
// ---------------------------------------------------------------------------
#define BM 128
#define BN 128
#define BK 8

__global__ __launch_bounds__(256) void k_gemm(const float* __restrict__ atoms)
{
    __shared__ float As[BK][BM];
    __shared__ float Bs[BK][BN];

    const int tid  = threadIdx.x;
    const int tcol = tid & 15;    // 0..15 (N)
    const int trow = tid >> 4;    // 0..15 (M)
    const int mBase = blockIdx.y * BM;
    const int nBase = blockIdx.x * BN;

    float acc[8][8];
    #pragma unroll
    for (int i = 0; i < 8; i++)
        #pragma unroll
        for (int j = 0; j < 8; j++) acc[i][j] = 0.f;

    const int aRow = tid >> 1;          // 0..127
    const int aCol = (tid & 1) * 4;     // 0 or 4
    const int bRow = tid >> 5;          // 0..7
    const int bCol = (tid & 31) * 4;    // 0..124

    const float* Ap = g_sel + (mBase + aRow) * N_ATOMS + aCol;
    const float* Bp = atoms + bRow * SAMPLES + nBase + bCol;

    for (int k0 = 0; k0 < N_ATOMS; k0 += BK) {
        float4 a4 = *(const float4*)(Ap + k0);
        As[aCol + 0][aRow] = a4.x;
        As[aCol + 1][aRow] = a4.y;
        As[aCol + 2][aRow] = a4.z;
        As[aCol + 3][aRow] = a4.w;
        float4 b4 = *(const float4*)(Bp + k0 * SAMPLES);
        *(float4*)&Bs[bRow][bCol] = b4;
        __syncthreads();

        #pragma unroll
        for (int k = 0; k < BK; k++) {
            float a[8], b[8];
            *(float4*)(a)     = *(const float4*)&As[k][trow * 8];
            *(float4*)(a + 4) = *(const float4*)&As[k][trow * 8 + 4];
            *(float4*)(b)     = *(const float4*)&Bs[k][tcol * 8];
            *(float4*)(b + 4) = *(const float4*)&Bs[k][tcol * 8 + 4];
            #pragma unroll
            for (int i = 0; i < 8; i++)
                #pragma unroll
                for (int j = 0; j < 8; j++)
                    acc[i][j] += a[i] * b[j];
        }
        __syncthreads();
    }

    float* Op = g_res + (mBase + trow * 8) * SAMPLES + nBase + tcol * 8;
    #pragma unroll
    for (int i = 0; i < 8; i++) {
        *(float4*)(Op + i * SAMPLES)     = make_float4(acc[i][0], acc[i][1], acc[i][2], acc[i][3]);
        *(float4*)(Op + i * SAMPLES + 4) = make_float4(acc[i][4], acc[i][5], acc[i][6], acc[i][7]);
    }
}

// ---------------------------------------------------------------------------
// K3: per-frame hann-weighted norm -> g_scale = mom/(norm+1e-8)
//     grid(frames=128, rows=1024), 128 threads (4 samples each, float4)
// ---------------------------------------------------------------------------
__global__ __launch_bounds__(128) void k_norm()
{
    const int f   = blockIdx.x;
    const int r   = blockIdx.y;
    const int tid = threadIdx.x;

    const int s0 = f * HOP + tid * 4;      // window position w = tid*4
    float sum = 0.f;
    if (s0 < SAMPLES) {                    // frame 127 tail reads zero-pad: skip
        float4 v = *(const float4*)(g_res + r * SAMPLES + s0);
        const int w = tid * 4;
        float h0 = g_hann[w + 0], h1 = g_hann[w + 1], h2 = g_hann[w + 2], h3 = g_hann[w + 3];
        float a0 = v.x * h0, a1 = v.y * h1, a2 = v.z * h2, a3 = v.w * h3;
        sum = a0 * a0 + a1 * a1 + a2 * a2 + a3 * a3;
    }
    // warp + block reduce (4 warps)
    #pragma unroll
    for (int o = 16; o > 0; o >>= 1) sum += __shfl_down_sync(0xffffffffu, sum, o);
    __shared__ float ws[4];
    if ((tid & 31) == 0) ws[tid >> 5] = sum;
    __syncthreads();
    if (tid == 0) {
        const float tot  = ws[0] + ws[1] + ws[2] + ws[3];
        const float norm = sqrtf(tot);
        g_scale[r * N_FRAMES + f] = g_mom[r * N_FRAMES + f] / (norm + 1e-8f);
    }
}

// ---------------------------------------------------------------------------
// K4: fused normalize + momentum + overlap-add (pointwise scale of res)
//     out[s] = res[s] * (hann[j]*g[f1] + hann[j+256]*g[f1-1]),  j=s%256, f1=s/256
//     grid(32, 1024), 256 threads, 4 samples each
// ---------------------------------------------------------------------------
__global__ __launch_bounds__(256) void k_final(float* __restrict__ out)
{
    const int r  = blockIdx.y;
    const int s0 = blockIdx.x * 1024 + threadIdx.x * 4;
    const int f1 = s0 >> 8;
    const int j  = s0 & 255;

    const float g1 = g_scale[r * N_FRAMES + f1];
    const float g0 = (f1 > 0) ? g_scale[r * N_FRAMES + f1 - 1] : 0.f;

    float4 v = *(const float4*)(g_res + r * SAMPLES + s0);
    float4 o;
    o.x = v.x * (g_hann[j + 0] * g1 + g_hann[j + 0 + HOP] * g0);
    o.y = v.y * (g_hann[j + 1] * g1 + g_hann[j + 1 + HOP] * g0);
    o.z = v.z * (g_hann[j + 2] * g1 + g_hann[j + 2 + HOP] * g0);
    o.w = v.w * (g_hann[j + 3] * g1 + g_hann[j + 3 + HOP] * g0);
    *(float4*)(out + r * SAMPLES + s0) = o;
}

// ---------------------------------------------------------------------------
extern "C" void kernel_launch(void* const* d_in, const int* in_sizes, int n_in,
                              void* d_out, int out_size)
{
    const float* x     = (const float*)d_in[0];
    const float* W_sel = (const float*)d_in[1];
    const float* b_sel = (const float*)d_in[2];
    const float* W_mom = (const float*)d_in[3];
    const float* b_mom = (const float*)d_in[4];
    const float* atoms = (const float*)d_in[5];

    float* out = (float*)d_out;
    const int audio_elems = R_ROWS * SAMPLES;                 // 33,554,432
    const int write_mom = (out_size >= audio_elems + R_ROWS * N_FRAMES) ? 1 : 0;
    float* out_mom = out + audio_elems;

    k_hann<<<1, WIN>>>();
    k_sel_mom<<<R_ROWS, 256>>>(x, W_sel, b_sel, W_mom, b_mom, out_mom, write_mom);
    k_gemm<<<dim3(SAMPLES / BN, R_ROWS / BM), 256>>>(atoms);
    k_norm<<<dim3(N_FRAMES, R_ROWS), 128>>>();
    k_final<<<dim3(SAMPLES / 1024, R_ROWS), 256>>>(out);
}

// round 4
// speedup vs baseline: 2.0029x; 2.0029x over previous
#include <cuda_runtime.h>
#include <cuda_bf16.h>
#include <math.h>
#include <stdint.h>

// Problem dims
#define R_ROWS   1024      // B*E = 16*64
#define LATENT   128
#define N_ATOMS  1024      // K of the big GEMM
#define N_FRAMES 128
#define SAMPLES  32768
#define WIN      512
#define HOP      256

// GEMM tiling
#define BM 128
#define BN 128
#define BK 32
#define NT (N_ATOMS / BK)      // 32 k-tiles
#define SM_PAD 8               // bf16 pad per row -> stride 40 el = 80 B
#define ROWB   80              // bytes per smem row
#define ARR_B  (128 * ROWB)    // 10240 B per matrix (Ah/Al/Bh/Bl)
#define STAGE_B (4 * ARR_B)    // 40960 B per stage
#define NSTAGE 3
#define GEMM_SMEM (NSTAGE * STAGE_B)

// Scratch (static device globals — no runtime allocation allowed)
__device__ __nv_bfloat16 g_selh[R_ROWS * N_ATOMS];     // 2 MB
__device__ __nv_bfloat16 g_sell[R_ROWS * N_ATOMS];     // 2 MB
__device__ __nv_bfloat16 g_ath [SAMPLES * N_ATOMS];    // atoms^T hi  64 MB
__device__ __nv_bfloat16 g_atl [SAMPLES * N_ATOMS];    // atoms^T lo  64 MB
__device__ float g_res[R_ROWS * SAMPLES];              // 128 MB
__device__ float g_mom[R_ROWS * N_FRAMES];
__device__ float g_scale[R_ROWS * N_FRAMES];
__device__ float g_hann[WIN];

// ---------------------------------------------------------------------------
// low-level helpers (all base-target sm_80+ instructions, no 'a' features)
// ---------------------------------------------------------------------------
__device__ __forceinline__ uint32_t smem_to_u32(const void* p) {
    uint32_t a;
    asm("{ .reg .u64 t; cvta.to.shared.u64 t, %1; cvt.u32.u64 %0, t; }" : "=r"(a) : "l"(p));
    return a;
}
#define CP_ASYNC16(dst, src) \
    asm volatile("cp.async.cg.shared.global [%0], [%1], 16;" :: "r"(dst), "l"(src))
#define CP_COMMIT()  asm volatile("cp.async.commit_group;" ::: "memory")
#define CP_WAIT1()   asm volatile("cp.async.wait_group 1;" ::: "memory")
#define CP_WAIT0()   asm volatile("cp.async.wait_group 0;" ::: "memory")

#define LDSM4(r, addr) \
    asm volatile("ldmatrix.sync.aligned.m8n8.x4.shared.b16 {%0,%1,%2,%3}, [%4];" \
        : "=r"((r)[0]), "=r"((r)[1]), "=r"((r)[2]), "=r"((r)[3]) : "r"(addr))

#define MMA_BF16(c, a, b0, b1) \
    asm volatile("mma.sync.aligned.m16n8k16.row.col.f32.bf16.bf16.f32 " \
        "{%0,%1,%2,%3},{%4,%5,%6,%7},{%8,%9},{%0,%1,%2,%3};" \
        : "+f"((c)[0]), "+f"((c)[1]), "+f"((c)[2]), "+f"((c)[3]) \
        : "r"((a)[0]), "r"((a)[1]), "r"((a)[2]), "r"((a)[3]), "r"(b0), "r"(b1))

// ---------------------------------------------------------------------------
// K0: hann window table (periodic)
// ---------------------------------------------------------------------------
__global__ void k_hann() {
    int w = threadIdx.x;
    if (w < WIN)
        g_hann[w] = 0.5f * (1.0f - cosf((float)(2.0 * 3.14159265358979323846 / (double)WIN) * (float)w));
}

// ---------------------------------------------------------------------------
// K_T: atoms [K=1024][S=32768] f32  ->  g_ath/g_atl [S][K] bf16 (split)
// ---------------------------------------------------------------------------
__global__ __launch_bounds__(256) void k_transpose(const float* __restrict__ atoms)
{
    __shared__ float ts[64][65];
    const int k0 = blockIdx.x * 64;
    const int n0 = blockIdx.y * 64;
    const int t  = threadIdx.x;

    {
        const int r = t >> 2, cs = (t & 3) * 16;
        const float4* src = (const float4*)(atoms + (size_t)(k0 + r) * SAMPLES + n0 + cs);
        #pragma unroll
        for (int j = 0; j < 4; j++) {
            float4 v = src[j];
            ts[r][cs + j * 4 + 0] = v.x; ts[r][cs + j * 4 + 1] = v.y;
            ts[r][cs + j * 4 + 2] = v.z; ts[r][cs + j * 4 + 3] = v.w;
        }
    }
    __syncthreads();
    {
        const int n = t >> 2, ks = (t & 3) * 16;
        uint32_t ph[8], pl[8];
        #pragma unroll
        for (int j = 0; j < 8; j++) {
            float v0 = ts[ks + 2 * j + 0][n];
            float v1 = ts[ks + 2 * j + 1][n];
            __nv_bfloat16 h0 = __float2bfloat16(v0);
            __nv_bfloat16 h1 = __float2bfloat16(v1);
            __nv_bfloat16 l0 = __float2bfloat16(v0 - __bfloat162float(h0));
            __nv_bfloat16 l1 = __float2bfloat16(v1 - __bfloat162float(h1));
            ph[j] = ((uint32_t)*(uint16_t*)&h0) | (((uint32_t)*(uint16_t*)&h1) << 16);
            pl[j] = ((uint32_t)*(uint16_t*)&l0) | (((uint32_t)*(uint16_t*)&l1) << 16);
        }
        uint4* dh = (uint4*)(g_ath + (size_t)(n0 + n) * N_ATOMS + k0 + ks);
        uint4* dl = (uint4*)(g_atl + (size_t)(n0 + n) * N_ATOMS + k0 + ks);
        dh[0] = make_uint4(ph[0], ph[1], ph[2], ph[3]);
        dh[1] = make_uint4(ph[4], ph[5], ph[6], ph[7]);
        dl[0] = make_uint4(pl[0], pl[1], pl[2], pl[3]);
        dl[1] = make_uint4(pl[4], pl[5], pl[6], pl[7]);
    }
}

// ---------------------------------------------------------------------------
// K1: per-row selection softmax (-> bf16 hi/lo) + momentum cumprod
// ---------------------------------------------------------------------------
__global__ __launch_bounds__(256) void k_sel_mom(
    const float* __restrict__ x,
    const float* __restrict__ W_sel, const float* __restrict__ b_sel,
    const float* __restrict__ W_mom, const float* __restrict__ b_mom,
    float* __restrict__ out_mom, int write_mom)
{
    __shared__ float xs[LATENT];
    __shared__ float red[256];
    __shared__ float lm[N_FRAMES];

    const int r   = blockIdx.x;
    const int tid = threadIdx.x;

    if (tid < LATENT) xs[tid] = x[r * LATENT + tid];
    __syncthreads();

    float z[4];
    #pragma unroll
    for (int i = 0; i < 4; i++) {
        const int a = tid + 256 * i;
        const float4* wp = (const float4*)(W_sel + a * LATENT);
        float acc = 0.f;
        #pragma unroll
        for (int l4 = 0; l4 < LATENT / 4; l4++) {
            float4 w4 = wp[l4];
            acc += xs[l4 * 4 + 0] * w4.x + xs[l4 * 4 + 1] * w4.y
                 + xs[l4 * 4 + 2] * w4.z + xs[l4 * 4 + 3] * w4.w;
        }
        z[i] = acc + b_sel[a];
    }

    float m = fmaxf(fmaxf(z[0], z[1]), fmaxf(z[2], z[3]));
    red[tid] = m; __syncthreads();
    for (int s = 128; s > 0; s >>= 1) { if (tid < s) red[tid] = fmaxf(red[tid], red[tid + s]); __syncthreads(); }
    m = red[0]; __syncthreads();

    float e[4], psum = 0.f;
    #pragma unroll
    for (int i = 0; i < 4; i++) { e[i] = expf(z[i] - m); psum += e[i]; }
    red[tid] = psum; __syncthreads();
    for (int s = 128; s > 0; s >>= 1) { if (tid < s) red[tid] += red[tid + s]; __syncthreads(); }
    const float inv = 1.0f / red[0];
    #pragma unroll
    for (int i = 0; i < 4; i++) {
        const float v = e[i] * inv;
        __nv_bfloat16 h = __float2bfloat16(v);
        __nv_bfloat16 l = __float2bfloat16(v - __bfloat162float(h));
        g_selh[r * N_ATOMS + tid + 256 * i] = h;
        g_sell[r * N_ATOMS + tid + 256 * i] = l;
    }

    if (tid < N_FRAMES) {
        const float4* wp = (const float4*)(W_mom + tid * LATENT);
        float acc = 0.f;
        #pragma unroll
        for (int l4 = 0; l4 < LATENT / 4; l4++) {
            float4 w4 = wp[l4];
            acc += xs[l4 * 4 + 0] * w4.x + xs[l4 * 4 + 1] * w4.y
                 + xs[l4 * 4 + 2] * w4.z + xs[l4 * 4 + 3] * w4.w;
        }
        acc += b_mom[tid];
        const float sg = 1.0f / (1.0f + expf(-acc));
        lm[tid] = logf(1e-12f + 0.2f + 0.72f * sg);
    }
    __syncthreads();
    if (tid == 0) {
        float c = 0.f;
        for (int f = 0; f < N_FRAMES; f++) {
            c += lm[f];
            const float mm = expf(c);
            g_mom[r * N_FRAMES + f] = mm;
            if (write_mom) out_mom[r * N_FRAMES + f] = mm;
        }
    }
}

// ---------------------------------------------------------------------------
// K2: res = sel @ atoms, warp-level HMMA, split-bf16 3-pass.
//     CTA 128x128, BK=32, 8 warps (warp tile 64x32), 3-stage cp.async.
//     smem per stage: [Ah|Al|Bh|Bl], each 128 rows x (32+8) bf16 (80 B rows).
// ---------------------------------------------------------------------------
__global__ __launch_bounds__(256, 1) void k_gemm()
{
    extern __shared__ char sm_dyn[];
    const uint32_t smem_u = smem_to_u32(sm_dyn);

    const int tid  = threadIdx.x;
    const int wid  = tid >> 5;
    const int lane = tid & 31;
    const int wm   = wid & 1;        // 2 warps in M  (64 rows each)
    const int wn   = wid >> 1;       // 4 warps in N  (32 cols each)
    const int mBase = blockIdx.x * BM;
    const int nBase = blockIdx.y * BN;

    // ---- per-thread gmem->smem copy descriptors (8 x 16B per stage) ----
    const __nv_bfloat16* srcp[8];
    uint32_t dstoff[8];
    #pragma unroll
    for (int i = 0; i < 8; i++) {
        const int q   = tid + i * 256;
        const int arr = q >> 9;           // 0 Ah, 1 Al, 2 Bh, 3 Bl
        const int qq  = q & 511;
        const int row = qq >> 2;
        const int c16 = qq & 3;
        const __nv_bfloat16* base =
            (arr == 0) ? g_selh : (arr == 1) ? g_sell : (arr == 2) ? g_ath : g_atl;
        const int grow = (arr < 2) ? (mBase + row) : (nBase + row);
        srcp[i]   = base + (size_t)grow * N_ATOMS + c16 * 8;
        dstoff[i] = (uint32_t)(arr * ARR_B + row * ROWB + c16 * 16);
    }

    #define LOAD_STAGE(buf, kc) do {                                     \
        const uint32_t sb_ = smem_u + (uint32_t)(buf) * STAGE_B;         \
        _Pragma("unroll")                                                \
        for (int i_ = 0; i_ < 8; i_++)                                   \
            CP_ASYNC16(sb_ + dstoff[i_], srcp[i_] + (kc));               \
        CP_COMMIT();                                                     \
    } while (0)

    // ---- ldmatrix lane offsets ----
    const uint32_t aoff = (uint32_t)((lane & 15) * ROWB + (lane >> 4) * 16);
    const uint32_t boff = (uint32_t)((((lane >> 4) * 8) + (lane & 7)) * ROWB
                                     + ((lane >> 3) & 1) * 16);

    float c[4][4][4];
    #pragma unroll
    for (int mi = 0; mi < 4; mi++)
        #pragma unroll
        for (int ni = 0; ni < 4; ni++)
            #pragma unroll
            for (int k = 0; k < 4; k++) c[mi][ni][k] = 0.f;

    LOAD_STAGE(0, 0);
    LOAD_STAGE(1, BK);

    for (int t = 0; t < NT; t++) {
        if (t == NT - 1) { CP_WAIT0(); } else { CP_WAIT1(); }
        __syncthreads();
        if (t + 2 < NT) LOAD_STAGE((t + 2) % NSTAGE, (t + 2) * BK);

        const uint32_t buf = smem_u + (uint32_t)(t % NSTAGE) * STAGE_B;

        #pragma unroll
        for (int ks = 0; ks < 2; ks++) {          // two k16 steps in BK=32
            uint32_t ah[4][4], al[4][4], bh[2][4], bl[2][4];
            #pragma unroll
            for (int mi = 0; mi < 4; mi++) {
                const uint32_t a_addr = buf + (uint32_t)((wm * 64 + mi * 16) * ROWB + ks * 32) + aoff;
                LDSM4(ah[mi], a_addr);
                LDSM4(al[mi], a_addr + ARR_B);
            }
            #pragma unroll
            for (int n2 = 0; n2 < 2; n2++) {
                const uint32_t b_addr = buf + (uint32_t)(2 * ARR_B + (wn * 32 + n2 * 16) * ROWB + ks * 32) + boff;
                LDSM4(bh[n2], b_addr);
                LDSM4(bl[n2], b_addr + ARR_B);
            }
            #pragma unroll
            for (int mi = 0; mi < 4; mi++)
                #pragma unroll
                for (int n2 = 0; n2 < 2; n2++)
                    #pragma unroll
                    for (int j = 0; j < 2; j++) {
                        const int ni = n2 * 2 + j;
                        MMA_BF16(c[mi][ni], ah[mi], bh[n2][2 * j], bh[n2][2 * j + 1]);
                        MMA_BF16(c[mi][ni], ah[mi], bl[n2][2 * j], bl[n2][2 * j + 1]);
                        MMA_BF16(c[mi][ni], al[mi], bh[n2][2 * j], bh[n2][2 * j + 1]);
                    }
        }
    }

    // ---- epilogue: write C frags straight to g_res ----
    const int rbase = mBase + wm * 64 + (lane >> 2);
    const int cbase = nBase + wn * 32 + (lane & 3) * 2;
    #pragma unroll
    for (int mi = 0; mi < 4; mi++)
        #pragma unroll
        for (int ni = 0; ni < 4; ni++) {
            float* p = g_res + (size_t)(rbase + mi * 16) * SAMPLES + cbase + ni * 8;
            *(float2*)p                 = make_float2(c[mi][ni][0], c[mi][ni][1]);
            *(float2*)(p + 8 * SAMPLES) = make_float2(c[mi][ni][2], c[mi][ni][3]);
        }
    #undef LOAD_STAGE
}

// ---------------------------------------------------------------------------
// K3: per-frame hann-weighted norm. One block per row, warp per frame.
// ---------------------------------------------------------------------------
__global__ __launch_bounds__(256) void k_norm()
{
    __shared__ float hs[WIN];
    const int r   = blockIdx.x;
    const int tid = threadIdx.x;
    const int w   = tid >> 5;
    const int l   = tid & 31;
    hs[tid] = g_hann[tid]; hs[tid + 256] = g_hann[tid + 256];
    __syncthreads();

    for (int f = w; f < N_FRAMES; f += 8) {
        float sum = 0.f;
        const int base = f * HOP + l * 16;
        #pragma unroll
        for (int j4 = 0; j4 < 4; j4++) {
            const int s = base + j4 * 4;
            if (s < SAMPLES) {
                float4 v = *(const float4*)(g_res + (size_t)r * SAMPLES + s);
                const int wp = l * 16 + j4 * 4;
                float a0 = v.x * hs[wp + 0], a1 = v.y * hs[wp + 1];
                float a2 = v.z * hs[wp + 2], a3 = v.w * hs[wp + 3];
                sum += a0 * a0 + a1 * a1 + a2 * a2 + a3 * a3;
            }
        }
        #pragma unroll
        for (int o = 16; o > 0; o >>= 1) sum += __shfl_down_sync(0xffffffffu, sum, o);
        if (l == 0)
            g_scale[r * N_FRAMES + f] = g_mom[r * N_FRAMES + f] / (sqrtf(sum) + 1e-8f);
    }
}

// ---------------------------------------------------------------------------
// K4: fused normalize + momentum + overlap-add (pointwise scale of res)
// ---------------------------------------------------------------------------
__global__ __launch_bounds__(256) void k_final(float* __restrict__ out)
{
    const int r  = blockIdx.y;
    const int s0 = blockIdx.x * 1024 + threadIdx.x * 4;
    const int f1 = s0 >> 8;
    const int j  = s0 & 255;

    const float g1 = g_scale[r * N_FRAMES + f1];
    const float g0 = (f1 > 0) ? g_scale[r * N_FRAMES + f1 - 1] : 0.f;

    float4 v = *(const float4*)(g_res + (size_t)r * SAMPLES + s0);
    float4 o;
    o.x = v.x * (g_hann[j + 0] * g1 + g_hann[j + 0 + HOP] * g0);
    o.y = v.y * (g_hann[j + 1] * g1 + g_hann[j + 1 + HOP] * g0);
    o.z = v.z * (g_hann[j + 2] * g1 + g_hann[j + 2 + HOP] * g0);
    o.w = v.w * (g_hann[j + 3] * g1 + g_hann[j + 3 + HOP] * g0);
    *(float4*)(out + (size_t)r * SAMPLES + s0) = o;
}

// ---------------------------------------------------------------------------
extern "C" void kernel_launch(void* const* d_in, const int* in_sizes, int n_in,
                              void* d_out, int out_size)
{
    const float* x     = (const float*)d_in[0];
    const float* W_sel = (const float*)d_in[1];
    const float* b_sel = (const float*)d_in[2];
    const float* W_mom = (const float*)d_in[3];
    const float* b_mom = (const float*)d_in[4];
    const float* atoms = (const float*)d_in[5];

    float* out = (float*)d_out;
    const int audio_elems = R_ROWS * SAMPLES;
    const int write_mom = (out_size >= audio_elems + R_ROWS * N_FRAMES) ? 1 : 0;
    float* out_mom = out + audio_elems;

    cudaFuncSetAttribute(k_gemm, cudaFuncAttributeMaxDynamicSharedMemorySize, GEMM_SMEM);

    k_hann<<<1, WIN>>>();
    k_transpose<<<dim3(N_ATOMS / 64, SAMPLES / 64), 256>>>(atoms);
    k_sel_mom<<<R_ROWS, 256>>>(x, W_sel, b_sel, W_mom, b_mom, out_mom, write_mom);
    // grid.x = M tiles (8) fastest -> CTAs sharing an atoms N-strip run together (L2 reuse)
    k_gemm<<<dim3(R_ROWS / BM, SAMPLES / BN), 256, GEMM_SMEM>>>();
    k_norm<<<R_ROWS, 256>>>();
    k_final<<<dim3(SAMPLES / 1024, R_ROWS), 256>>>(out);
}

// round 6
// speedup vs baseline: 2.1613x; 1.0791x over previous
#include <cuda_runtime.h>
#include <cuda_bf16.h>
#include <math.h>
#include <stdint.h>

// Problem dims
#define R_ROWS   1024      // B*E = 16*64
#define LATENT   128
#define N_ATOMS  1024      // K of the big GEMM
#define N_FRAMES 128
#define SAMPLES  32768
#define WIN      512
#define HOP      256

// GEMM tiling: CTA 128x256, BK=32, 8 warps (warp tile 64x64)
#define BM 128
#define BN 256
#define BK 32
#define NT (N_ATOMS / BK)      // 32 k-tiles
#define ROWB   80              // bytes per smem row (32 bf16 + 8 pad)
#define A_B    (128 * ROWB)    // 10240 B (Ah or Al)
#define B_B    (256 * ROWB)    // 20480 B (Bh or Bl)
#define OFF_AH 0
#define OFF_AL (A_B)
#define OFF_BH (2 * A_B)
#define OFF_BL (2 * A_B + B_B)
#define STAGE_B (2 * A_B + 2 * B_B)   // 61440
#define NSTAGE 3
#define GEMM_SMEM (NSTAGE * STAGE_B)  // 184320

// Scratch (static device globals — no runtime allocation allowed)
__device__ __nv_bfloat16 g_selh[R_ROWS * N_ATOMS];     // 2 MB
__device__ __nv_bfloat16 g_sell[R_ROWS * N_ATOMS];     // 2 MB
__device__ __nv_bfloat16 g_ath [SAMPLES * N_ATOMS];    // atoms^T hi  64 MB
__device__ __nv_bfloat16 g_atl [SAMPLES * N_ATOMS];    // atoms^T lo  64 MB
__device__ float g_res[R_ROWS * SAMPLES];              // 128 MB
__device__ float g_mom[R_ROWS * N_FRAMES];
__device__ float g_scale[R_ROWS * N_FRAMES];
__device__ float g_hann[WIN];

// ---------------------------------------------------------------------------
// low-level helpers (base-target sm_80+ instructions only)
// ---------------------------------------------------------------------------
__device__ __forceinline__ uint32_t smem_to_u32(const void* p) {
    uint32_t a;
    asm("{ .reg .u64 t; cvta.to.shared.u64 t, %1; cvt.u32.u64 %0, t; }" : "=r"(a) : "l"(p));
    return a;
}
#define CP_ASYNC16(dst, src) \
    asm volatile("cp.async.cg.shared.global [%0], [%1], 16;" :: "r"(dst), "l"(src))
#define CP_COMMIT()  asm volatile("cp.async.commit_group;" ::: "memory")
#define CP_WAIT1()   asm volatile("cp.async.wait_group 1;" ::: "memory")
#define CP_WAIT0()   asm volatile("cp.async.wait_group 0;" ::: "memory")

#define LDSM4(r, addr) \
    asm volatile("ldmatrix.sync.aligned.m8n8.x4.shared.b16 {%0,%1,%2,%3}, [%4];" \
        : "=r"((r)[0]), "=r"((r)[1]), "=r"((r)[2]), "=r"((r)[3]) : "r"(addr))

#define MMA_BF16(c, a, b0, b1) \
    asm volatile("mma.sync.aligned.m16n8k16.row.col.f32.bf16.bf16.f32 " \
        "{%0,%1,%2,%3},{%4,%5,%6,%7},{%8,%9},{%0,%1,%2,%3};" \
        : "+f"((c)[0]), "+f"((c)[1]), "+f"((c)[2]), "+f"((c)[3]) \
        : "r"((a)[0]), "r"((a)[1]), "r"((a)[2]), "r"((a)[3]), "r"(b0), "r"(b1))

// ---------------------------------------------------------------------------
// K0: hann window table (periodic)
// ---------------------------------------------------------------------------
__global__ void k_hann() {
    int w = threadIdx.x;
    if (w < WIN)
        g_hann[w] = 0.5f * (1.0f - cosf((float)(2.0 * 3.14159265358979323846 / (double)WIN) * (float)w));
}

// ---------------------------------------------------------------------------
// K_T: atoms [K=1024][S=32768] f32  ->  g_ath/g_atl [S][K] bf16 (split)
// ---------------------------------------------------------------------------
__global__ __launch_bounds__(256) void k_transpose(const float* __restrict__ atoms)
{
    __shared__ float ts[64][65];
    const int k0 = blockIdx.x * 64;
    const int n0 = blockIdx.y * 64;
    const int t  = threadIdx.x;

    {
        const int r = t >> 2, cs = (t & 3) * 16;
        const float4* src = (const float4*)(atoms + (size_t)(k0 + r) * SAMPLES + n0 + cs);
        #pragma unroll
        for (int j = 0; j < 4; j++) {
            float4 v = src[j];
            ts[r][cs + j * 4 + 0] = v.x; ts[r][cs + j * 4 + 1] = v.y;
            ts[r][cs + j * 4 + 2] = v.z; ts[r][cs + j * 4 + 3] = v.w;
        }
    }
    __syncthreads();
    {
        const int n = t >> 2, ks = (t & 3) * 16;
        uint32_t ph[8], pl[8];
        #pragma unroll
        for (int j = 0; j < 8; j++) {
            float v0 = ts[ks + 2 * j + 0][n];
            float v1 = ts[ks + 2 * j + 1][n];
            __nv_bfloat16 h0 = __float2bfloat16(v0);
            __nv_bfloat16 h1 = __float2bfloat16(v1);
            __nv_bfloat16 l0 = __float2bfloat16(v0 - __bfloat162float(h0));
            __nv_bfloat16 l1 = __float2bfloat16(v1 - __bfloat162float(h1));
            ph[j] = ((uint32_t)*(uint16_t*)&h0) | (((uint32_t)*(uint16_t*)&h1) << 16);
            pl[j] = ((uint32_t)*(uint16_t*)&l0) | (((uint32_t)*(uint16_t*)&l1) << 16);
        }
        uint4* dh = (uint4*)(g_ath + (size_t)(n0 + n) * N_ATOMS + k0 + ks);
        uint4* dl = (uint4*)(g_atl + (size_t)(n0 + n) * N_ATOMS + k0 + ks);
        dh[0] = make_uint4(ph[0], ph[1], ph[2], ph[3]);
        dh[1] = make_uint4(ph[4], ph[5], ph[6], ph[7]);
        dl[0] = make_uint4(pl[0], pl[1], pl[2], pl[3]);
        dl[1] = make_uint4(pl[4], pl[5], pl[6], pl[7]);
    }
}

// ---------------------------------------------------------------------------
// K1: per-row selection softmax (-> bf16 hi/lo) + momentum cumprod
// ---------------------------------------------------------------------------
__global__ __launch_bounds__(256) void k_sel_mom(
    const float* __restrict__ x,
    const float* __restrict__ W_sel, const float* __restrict__ b_sel,
    const float* __restrict__ W_mom, const float* __restrict__ b_mom,
    float* __restrict__ out_mom, int write_mom)
{
    __shared__ float xs[LATENT];
    __shared__ float red[256];
    __shared__ float lm[N_FRAMES];

    const int r   = blockIdx.x;
    const int tid = threadIdx.x;

    if (tid < LATENT) xs[tid] = x[r * LATENT + tid];
    __syncthreads();

    float z[4];
    #pragma unroll
    for (int i = 0; i < 4; i++) {
        const int a = tid + 256 * i;
        const float4* wp = (const float4*)(W_sel + a * LATENT);
        float acc = 0.f;
        #pragma unroll
        for (int l4 = 0; l4 < LATENT / 4; l4++) {
            float4 w4 = wp[l4];
            acc += xs[l4 * 4 + 0] * w4.x + xs[l4 * 4 + 1] * w4.y
                 + xs[l4 * 4 + 2] * w4.z + xs[l4 * 4 + 3] * w4.w;
        }
        z[i] = acc + b_sel[a];
    }

    float m = fmaxf(fmaxf(z[0], z[1]), fmaxf(z[2], z[3]));
    red[tid] = m; __syncthreads();
    for (int s = 128; s > 0; s >>= 1) { if (tid < s) red[tid] = fmaxf(red[tid], red[tid + s]); __syncthreads(); }
    m = red[0]; __syncthreads();

    float e[4], psum = 0.f;
    #pragma unroll
    for (int i = 0; i < 4; i++) { e[i] = expf(z[i] - m); psum += e[i]; }
    red[tid] = psum; __syncthreads();
    for (int s = 128; s > 0; s >>= 1) { if (tid < s) red[tid] += red[tid + s]; __syncthreads(); }
    const float inv = 1.0f / red[0];
    #pragma unroll
    for (int i = 0; i < 4; i++) {
        const float v = e[i] * inv;
        __nv_bfloat16 h = __float2bfloat16(v);
        __nv_bfloat16 l = __float2bfloat16(v - __bfloat162float(h));
        g_selh[r * N_ATOMS + tid + 256 * i] = h;
        g_sell[r * N_ATOMS + tid + 256 * i] = l;
    }

    if (tid < N_FRAMES) {
        const float4* wp = (const float4*)(W_mom + tid * LATENT);
        float acc = 0.f;
        #pragma unroll
        for (int l4 = 0; l4 < LATENT / 4; l4++) {
            float4 w4 = wp[l4];
            acc += xs[l4 * 4 + 0] * w4.x + xs[l4 * 4 + 1] * w4.y
                 + xs[l4 * 4 + 2] * w4.z + xs[l4 * 4 + 3] * w4.w;
        }
        acc += b_mom[tid];
        const float sg = 1.0f / (1.0f + expf(-acc));
        lm[tid] = logf(1e-12f + 0.2f + 0.72f * sg);
    }
    __syncthreads();
    if (tid == 0) {
        float c = 0.f;
        for (int f = 0; f < N_FRAMES; f++) {
            c += lm[f];
            const float mm = expf(c);
            g_mom[r * N_FRAMES + f] = mm;
            if (write_mom) out_mom[r * N_FRAMES + f] = mm;
        }
    }
}

// ---------------------------------------------------------------------------
// K2: res = sel @ atoms, warp HMMA, split-bf16 3-pass, CTA 128x256, warp 64x64
// ---------------------------------------------------------------------------
__global__ __launch_bounds__(256, 1) void k_gemm()
{
    extern __shared__ char sm_dyn[];
    const uint32_t smem_u = smem_to_u32(sm_dyn);

    const int tid  = threadIdx.x;
    const int wid  = tid >> 5;
    const int lane = tid & 31;
    const int wm   = wid & 1;        // 2 warps in M  (64 rows)
    const int wn   = wid >> 1;       // 4 warps in N  (64 cols)
    const int mBase = blockIdx.x * BM;
    const int nBase = blockIdx.y * BN;

    // ---- per-thread gmem->smem copy descriptors (12 x 16B per stage) ----
    // chunks: 0..511 Ah, 512..1023 Al, 1024..2047 Bh, 2048..3071 Bl
    const __nv_bfloat16* srcp[12];
    uint32_t dstoff[12];
    #pragma unroll
    for (int i = 0; i < 12; i++) {
        const int q = tid + i * 256;
        const __nv_bfloat16* base;
        int row, c16, off0;
        if (q < 1024) {
            base = (q < 512) ? g_selh : g_sell;
            const int qq = q & 511;
            row = qq >> 2; c16 = qq & 3;
            off0 = (q < 512) ? OFF_AH : OFF_AL;
            srcp[i] = base + (size_t)(mBase + row) * N_ATOMS + c16 * 8;
        } else {
            const int q2 = q - 1024;
            base = (q2 < 1024) ? g_ath : g_atl;
            const int qq = q2 & 1023;
            row = qq >> 2; c16 = qq & 3;
            off0 = (q2 < 1024) ? OFF_BH : OFF_BL;
            srcp[i] = base + (size_t)(nBase + row) * N_ATOMS + c16 * 8;
        }
        dstoff[i] = (uint32_t)(off0 + row * ROWB + c16 * 16);
    }

    #define LOAD_STAGE(buf, kc) do {                                     \
        const uint32_t sb_ = smem_u + (uint32_t)(buf) * STAGE_B;         \
        _Pragma("unroll")                                                \
        for (int i_ = 0; i_ < 12; i_++)                                  \
            CP_ASYNC16(sb_ + dstoff[i_], srcp[i_] + (kc));               \
        CP_COMMIT();                                                     \
    } while (0)

    // ---- ldmatrix lane offsets ----
    const uint32_t aoff = (uint32_t)((lane & 15) * ROWB + (lane >> 4) * 16);
    const uint32_t boff = (uint32_t)((((lane >> 4) * 8) + (lane & 7)) * ROWB
                                     + ((lane >> 3) & 1) * 16);

    float c[4][8][4];
    #pragma unroll
    for (int mi = 0; mi < 4; mi++)
        #pragma unroll
        for (int ni = 0; ni < 8; ni++)
            #pragma unroll
            for (int k = 0; k < 4; k++) c[mi][ni][k] = 0.f;

    LOAD_STAGE(0, 0);
    LOAD_STAGE(1, BK);

    for (int t = 0; t < NT; t++) {
        if (t == NT - 1) { CP_WAIT0(); } else { CP_WAIT1(); }
        __syncthreads();
        if (t + 2 < NT) LOAD_STAGE((t + 2) % NSTAGE, (t + 2) * BK);

        const uint32_t buf = smem_u + (uint32_t)(t % NSTAGE) * STAGE_B;

        #pragma unroll
        for (int ks = 0; ks < 2; ks++) {          // two k16 steps in BK=32
            uint32_t ah[4][4], al[4][4], bh[4][4], bl[4][4];
            #pragma unroll
            for (int mi = 0; mi < 4; mi++) {
                const uint32_t a_addr = buf + (uint32_t)((wm * 64 + mi * 16) * ROWB + ks * 32) + aoff;
                LDSM4(ah[mi], a_addr);
                LDSM4(al[mi], a_addr + A_B);
            }
            #pragma unroll
            for (int nb = 0; nb < 4; nb++) {
                const uint32_t b_addr = buf + (uint32_t)(OFF_BH + (wn * 64 + nb * 16) * ROWB + ks * 32) + boff;
                LDSM4(bh[nb], b_addr);
                LDSM4(bl[nb], b_addr + B_B);
            }
            // pass-outermost: consecutive MMAs hit distinct accumulators
            #pragma unroll
            for (int mi = 0; mi < 4; mi++)
                #pragma unroll
                for (int nb = 0; nb < 4; nb++)
                    #pragma unroll
                    for (int j = 0; j < 2; j++)
                        MMA_BF16(c[mi][nb * 2 + j], ah[mi], bh[nb][2 * j], bh[nb][2 * j + 1]);
            #pragma unroll
            for (int mi = 0; mi < 4; mi++)
                #pragma unroll
                for (int nb = 0; nb < 4; nb++)
                    #pragma unroll
                    for (int j = 0; j < 2; j++)
                        MMA_BF16(c[mi][nb * 2 + j], ah[mi], bl[nb][2 * j], bl[nb][2 * j + 1]);
            #pragma unroll
            for (int mi = 0; mi < 4; mi++)
                #pragma unroll
                for (int nb = 0; nb < 4; nb++)
                    #pragma unroll
                    for (int j = 0; j < 2; j++)
                        MMA_BF16(c[mi][nb * 2 + j], al[mi], bh[nb][2 * j], bh[nb][2 * j + 1]);
        }
    }

    // ---- epilogue: write C frags straight to g_res ----
    const int rbase = mBase + wm * 64 + (lane >> 2);
    const int cbase = nBase + wn * 64 + (lane & 3) * 2;
    #pragma unroll
    for (int mi = 0; mi < 4; mi++)
        #pragma unroll
        for (int ni = 0; ni < 8; ni++) {
            float* p = g_res + (size_t)(rbase + mi * 16) * SAMPLES + cbase + ni * 8;
            *(float2*)p                 = make_float2(c[mi][ni][0], c[mi][ni][1]);
            *(float2*)(p + 8 * SAMPLES) = make_float2(c[mi][ni][2], c[mi][ni][3]);
        }
    #undef LOAD_STAGE
}

// ---------------------------------------------------------------------------
// K3: per-frame hann-weighted norm. One block per row, warp per frame.
// ---------------------------------------------------------------------------
__global__ __launch_bounds__(256) void k_norm()
{
    __shared__ float hs[WIN];
    const int r   = blockIdx.x;
    const int tid = threadIdx.x;
    const int w   = tid >> 5;
    const int l   = tid & 31;
    hs[tid] = g_hann[tid]; hs[tid + 256] = g_hann[tid + 256];
    __syncthreads();

    for (int f = w; f < N_FRAMES; f += 8) {
        float sum = 0.f;
        const int base = f * HOP + l * 16;
        #pragma unroll
        for (int j4 = 0; j4 < 4; j4++) {
            const int s = base + j4 * 4;
            if (s < SAMPLES) {
                float4 v = *(const float4*)(g_res + (size_t)r * SAMPLES + s);
                const int wp = l * 16 + j4 * 4;
                float a0 = v.x * hs[wp + 0], a1 = v.y * hs[wp + 1];
                float a2 = v.z * hs[wp + 2], a3 = v.w * hs[wp + 3];
                sum += a0 * a0 + a1 * a1 + a2 * a2 + a3 * a3;
            }
        }
        #pragma unroll
        for (int o = 16; o > 0; o >>= 1) sum += __shfl_down_sync(0xffffffffu, sum, o);
        if (l == 0)
            g_scale[r * N_FRAMES + f] = g_mom[r * N_FRAMES + f] / (sqrtf(sum) + 1e-8f);
    }
}

// ---------------------------------------------------------------------------
// K4: fused normalize + momentum + overlap-add (pointwise scale of res)
// ---------------------------------------------------------------------------
__global__ __launch_bounds__(256) void k_final(float* __restrict__ out)
{
    const int r  = blockIdx.y;
    const int s0 = blockIdx.x * 1024 + threadIdx.x * 4;
    const int f1 = s0 >> 8;
    const int j  = s0 & 255;

    const float g1 = g_scale[r * N_FRAMES + f1];
    const float g0 = (f1 > 0) ? g_scale[r * N_FRAMES + f1 - 1] : 0.f;

    float4 v = *(const float4*)(g_res + (size_t)r * SAMPLES + s0);
    float4 o;
    o.x = v.x * (g_hann[j + 0] * g1 + g_hann[j + 0 + HOP] * g0);
    o.y = v.y * (g_hann[j + 1] * g1 + g_hann[j + 1 + HOP] * g0);
    o.z = v.z * (g_hann[j + 2] * g1 + g_hann[j + 2 + HOP] * g0);
    o.w = v.w * (g_hann[j + 3] * g1 + g_hann[j + 3 + HOP] * g0);
    *(float4*)(out + (size_t)r * SAMPLES + s0) = o;
}

// ---------------------------------------------------------------------------
extern "C" void kernel_launch(void* const* d_in, const int* in_sizes, int n_in,
                              void* d_out, int out_size)
{
    const float* x     = (const float*)d_in[0];
    const float* W_sel = (const float*)d_in[1];
    const float* b_sel = (const float*)d_in[2];
    const float* W_mom = (const float*)d_in[3];
    const float* b_mom = (const float*)d_in[4];
    const float* atoms = (const float*)d_in[5];

    float* out = (float*)d_out;
    const int audio_elems = R_ROWS * SAMPLES;
    const int write_mom = (out_size >= audio_elems + R_ROWS * N_FRAMES) ? 1 : 0;
    float* out_mom = out + audio_elems;

    cudaFuncSetAttribute(k_gemm, cudaFuncAttributeMaxDynamicSharedMemorySize, GEMM_SMEM);

    k_hann<<<1, WIN>>>();
    k_transpose<<<dim3(N_ATOMS / 64, SAMPLES / 64), 256>>>(atoms);
    k_sel_mom<<<R_ROWS, 256>>>(x, W_sel, b_sel, W_mom, b_mom, out_mom, write_mom);
    // grid.x = M tiles (8) fastest -> CTAs sharing an atoms N-strip run together (L2 reuse)
    k_gemm<<<dim3(R_ROWS / BM, SAMPLES / BN), 256, GEMM_SMEM>>>();
    k_norm<<<R_ROWS, 256>>>();
    k_final<<<dim3(SAMPLES / 1024, R_ROWS), 256>>>(out);
}

// round 7
// speedup vs baseline: 2.3451x; 1.0851x over previous
#include <cuda_runtime.h>
#include <cuda_bf16.h>
#include <math.h>
#include <stdint.h>

// Problem dims
#define R_ROWS   1024      // B*E = 16*64
#define LATENT   128
#define N_ATOMS  1024      // K of the big GEMM
#define N_FRAMES 128
#define SAMPLES  32768
#define WIN      512
#define HOP      256

// GEMM tiling: CTA 128x128, BK=32, 8 warps (warp tile 64x32), 2 CTAs/SM
#define BM 128
#define BN 128
#define BK 32
#define NT (N_ATOMS / BK)      // 32 k-tiles
#define ROWB   80              // bytes per smem row (32 bf16 + 8 pad)
#define ARR_B  (128 * ROWB)    // 10240 B per matrix
#define OFF_AH 0
#define OFF_AL (ARR_B)
#define OFF_BH (2 * ARR_B)
#define OFF_BL (3 * ARR_B)
#define STAGE_B (4 * ARR_B)    // 40960
#define NSTAGE 2
#define GEMM_SMEM (NSTAGE * STAGE_B)  // 81920 per CTA

// Scratch (static device globals — no runtime allocation allowed)
__device__ __nv_bfloat16 g_selh[R_ROWS * N_ATOMS];     // 2 MB
__device__ __nv_bfloat16 g_sell[R_ROWS * N_ATOMS];     // 2 MB
__device__ __nv_bfloat16 g_ath [SAMPLES * N_ATOMS];    // atoms^T hi  64 MB
__device__ __nv_bfloat16 g_atl [SAMPLES * N_ATOMS];    // atoms^T lo  64 MB
__device__ float g_res[R_ROWS * SAMPLES];              // 128 MB
__device__ float g_mom[R_ROWS * N_FRAMES];
__device__ float g_hann[WIN];

// ---------------------------------------------------------------------------
// low-level helpers (base-target sm_80+ instructions only)
// ---------------------------------------------------------------------------
__device__ __forceinline__ uint32_t smem_to_u32(const void* p) {
    uint32_t a;
    asm("{ .reg .u64 t; cvta.to.shared.u64 t, %1; cvt.u32.u64 %0, t; }" : "=r"(a) : "l"(p));
    return a;
}
#define CP_ASYNC16(dst, src) \
    asm volatile("cp.async.cg.shared.global [%0], [%1], 16;" :: "r"(dst), "l"(src))
#define CP_COMMIT()  asm volatile("cp.async.commit_group;" ::: "memory")
#define CP_WAIT1()   asm volatile("cp.async.wait_group 1;" ::: "memory")
#define CP_WAIT0()   asm volatile("cp.async.wait_group 0;" ::: "memory")

#define LDSM4(r, addr) \
    asm volatile("ldmatrix.sync.aligned.m8n8.x4.shared.b16 {%0,%1,%2,%3}, [%4];" \
        : "=r"((r)[0]), "=r"((r)[1]), "=r"((r)[2]), "=r"((r)[3]) : "r"(addr))

#define MMA_BF16(c, a, b0, b1) \
    asm volatile("mma.sync.aligned.m16n8k16.row.col.f32.bf16.bf16.f32 " \
        "{%0,%1,%2,%3},{%4,%5,%6,%7},{%8,%9},{%0,%1,%2,%3};" \
        : "+f"((c)[0]), "+f"((c)[1]), "+f"((c)[2]), "+f"((c)[3]) \
        : "r"((a)[0]), "r"((a)[1]), "r"((a)[2]), "r"((a)[3]), "r"(b0), "r"(b1))

// ---------------------------------------------------------------------------
// K0: hann window table (periodic)
// ---------------------------------------------------------------------------
__global__ void k_hann() {
    int w = threadIdx.x;
    if (w < WIN)
        g_hann[w] = 0.5f * (1.0f - cosf((float)(2.0 * 3.14159265358979323846 / (double)WIN) * (float)w));
}

// ---------------------------------------------------------------------------
// K_T: atoms [K=1024][S=32768] f32  ->  g_ath/g_atl [S][K] bf16 (split)
// ---------------------------------------------------------------------------
__global__ __launch_bounds__(256) void k_transpose(const float* __restrict__ atoms)
{
    __shared__ float ts[64][65];
    const int k0 = blockIdx.x * 64;
    const int n0 = blockIdx.y * 64;
    const int t  = threadIdx.x;

    {
        const int r = t >> 2, cs = (t & 3) * 16;
        const float4* src = (const float4*)(atoms + (size_t)(k0 + r) * SAMPLES + n0 + cs);
        #pragma unroll
        for (int j = 0; j < 4; j++) {
            float4 v = src[j];
            ts[r][cs + j * 4 + 0] = v.x; ts[r][cs + j * 4 + 1] = v.y;
            ts[r][cs + j * 4 + 2] = v.z; ts[r][cs + j * 4 + 3] = v.w;
        }
    }
    __syncthreads();
    {
        const int n = t >> 2, ks = (t & 3) * 16;
        uint32_t ph[8], pl[8];
        #pragma unroll
        for (int j = 0; j < 8; j++) {
            float v0 = ts[ks + 2 * j + 0][n];
            float v1 = ts[ks + 2 * j + 1][n];
            __nv_bfloat16 h0 = __float2bfloat16(v0);
            __nv_bfloat16 h1 = __float2bfloat16(v1);
            __nv_bfloat16 l0 = __float2bfloat16(v0 - __bfloat162float(h0));
            __nv_bfloat16 l1 = __float2bfloat16(v1 - __bfloat162float(h1));
            ph[j] = ((uint32_t)*(uint16_t*)&h0) | (((uint32_t)*(uint16_t*)&h1) << 16);
            pl[j] = ((uint32_t)*(uint16_t*)&l0) | (((uint32_t)*(uint16_t*)&l1) << 16);
        }
        uint4* dh = (uint4*)(g_ath + (size_t)(n0 + n) * N_ATOMS + k0 + ks);
        uint4* dl = (uint4*)(g_atl + (size_t)(n0 + n) * N_ATOMS + k0 + ks);
        dh[0] = make_uint4(ph[0], ph[1], ph[2], ph[3]);
        dh[1] = make_uint4(ph[4], ph[5], ph[6], ph[7]);
        dl[0] = make_uint4(pl[0], pl[1], pl[2], pl[3]);
        dl[1] = make_uint4(pl[4], pl[5], pl[6], pl[7]);
    }
}

// ---------------------------------------------------------------------------
// K1: per-row selection softmax (-> bf16 hi/lo) + momentum cumprod
// ---------------------------------------------------------------------------
__global__ __launch_bounds__(256) void k_sel_mom(
    const float* __restrict__ x,
    const float* __restrict__ W_sel, const float* __restrict__ b_sel,
    const float* __restrict__ W_mom, const float* __restrict__ b_mom,
    float* __restrict__ out_mom, int write_mom)
{
    __shared__ float xs[LATENT];
    __shared__ float red[256];
    __shared__ float lm[N_FRAMES];

    const int r   = blockIdx.x;
    const int tid = threadIdx.x;

    if (tid < LATENT) xs[tid] = x[r * LATENT + tid];
    __syncthreads();

    float z[4];
    #pragma unroll
    for (int i = 0; i < 4; i++) {
        const int a = tid + 256 * i;
        const float4* wp = (const float4*)(W_sel + a * LATENT);
        float acc = 0.f;
        #pragma unroll
        for (int l4 = 0; l4 < LATENT / 4; l4++) {
            float4 w4 = wp[l4];
            acc += xs[l4 * 4 + 0] * w4.x + xs[l4 * 4 + 1] * w4.y
                 + xs[l4 * 4 + 2] * w4.z + xs[l4 * 4 + 3] * w4.w;
        }
        z[i] = acc + b_sel[a];
    }

    float m = fmaxf(fmaxf(z[0], z[1]), fmaxf(z[2], z[3]));
    red[tid] = m; __syncthreads();
    for (int s = 128; s > 0; s >>= 1) { if (tid < s) red[tid] = fmaxf(red[tid], red[tid + s]); __syncthreads(); }
    m = red[0]; __syncthreads();

    float e[4], psum = 0.f;
    #pragma unroll
    for (int i = 0; i < 4; i++) { e[i] = expf(z[i] - m); psum += e[i]; }
    red[tid] = psum; __syncthreads();
    for (int s = 128; s > 0; s >>= 1) { if (tid < s) red[tid] += red[tid + s]; __syncthreads(); }
    const float inv = 1.0f / red[0];
    #pragma unroll
    for (int i = 0; i < 4; i++) {
        const float v = e[i] * inv;
        __nv_bfloat16 h = __float2bfloat16(v);
        __nv_bfloat16 l = __float2bfloat16(v - __bfloat162float(h));
        g_selh[r * N_ATOMS + tid + 256 * i] = h;
        g_sell[r * N_ATOMS + tid + 256 * i] = l;
    }

    if (tid < N_FRAMES) {
        const float4* wp = (const float4*)(W_mom + tid * LATENT);
        float acc = 0.f;
        #pragma unroll
        for (int l4 = 0; l4 < LATENT / 4; l4++) {
            float4 w4 = wp[l4];
            acc += xs[l4 * 4 + 0] * w4.x + xs[l4 * 4 + 1] * w4.y
                 + xs[l4 * 4 + 2] * w4.z + xs[l4 * 4 + 3] * w4.w;
        }
        acc += b_mom[tid];
        const float sg = 1.0f / (1.0f + expf(-acc));
        lm[tid] = logf(1e-12f + 0.2f + 0.72f * sg);
    }
    __syncthreads();
    if (tid == 0) {
        float c = 0.f;
        for (int f = 0; f < N_FRAMES; f++) {
            c += lm[f];
            const float mm = expf(c);
            g_mom[r * N_FRAMES + f] = mm;
            if (write_mom) out_mom[r * N_FRAMES + f] = mm;
        }
    }
}

// ---------------------------------------------------------------------------
// K2: res = sel @ atoms, warp HMMA, split-bf16 3-pass.
//     CTA 128x128, warp 64x32, 2 CTAs/SM (reg-capped), 2-stage cp.async.
// ---------------------------------------------------------------------------
__global__ __launch_bounds__(256, 2) void k_gemm()
{
    extern __shared__ char sm_dyn[];
    const uint32_t smem_u = smem_to_u32(sm_dyn);

    const int tid  = threadIdx.x;
    const int wid  = tid >> 5;
    const int lane = tid & 31;
    const int wm   = wid & 1;        // 2 warps in M  (64 rows)
    const int wn   = wid >> 1;       // 4 warps in N  (32 cols)
    const int mBase = blockIdx.x * BM;
    const int nBase = blockIdx.y * BN;

    // ---- per-thread gmem->smem copy descriptors (8 x 16B per stage) ----
    // chunks: 0..511 Ah, 512..1023 Al, 1024..1535 Bh, 1536..2047 Bl
    const __nv_bfloat16* srcp[8];
    uint32_t dstoff[8];
    #pragma unroll
    for (int i = 0; i < 8; i++) {
        const int q   = tid + i * 256;
        const int arr = q >> 9;           // 0 Ah, 1 Al, 2 Bh, 3 Bl
        const int qq  = q & 511;
        const int row = qq >> 2;
        const int c16 = qq & 3;
        const __nv_bfloat16* base =
            (arr == 0) ? g_selh : (arr == 1) ? g_sell : (arr == 2) ? g_ath : g_atl;
        const int grow = (arr < 2) ? (mBase + row) : (nBase + row);
        srcp[i]   = base + (size_t)grow * N_ATOMS + c16 * 8;
        dstoff[i] = (uint32_t)(arr * ARR_B + row * ROWB + c16 * 16);
    }

    #define LOAD_STAGE(buf, kc) do {                                     \
        const uint32_t sb_ = smem_u + (uint32_t)(buf) * STAGE_B;         \
        _Pragma("unroll")                                                \
        for (int i_ = 0; i_ < 8; i_++)                                   \
            CP_ASYNC16(sb_ + dstoff[i_], srcp[i_] + (kc));               \
        CP_COMMIT();                                                     \
    } while (0)

    // ---- ldmatrix lane offsets ----
    const uint32_t aoff = (uint32_t)((lane & 15) * ROWB + (lane >> 4) * 16);
    const uint32_t boff = (uint32_t)((((lane >> 4) * 8) + (lane & 7)) * ROWB
                                     + ((lane >> 3) & 1) * 16);

    float c[4][4][4];
    #pragma unroll
    for (int mi = 0; mi < 4; mi++)
        #pragma unroll
        for (int ni = 0; ni < 4; ni++)
            #pragma unroll
            for (int k = 0; k < 4; k++) c[mi][ni][k] = 0.f;

    LOAD_STAGE(0, 0);

    for (int t = 0; t < NT; t++) {
        if (t + 1 < NT) { LOAD_STAGE((t + 1) & 1, (t + 1) * BK); CP_WAIT1(); }
        else            { CP_WAIT0(); }
        __syncthreads();

        const uint32_t buf = smem_u + (uint32_t)(t & 1) * STAGE_B;

        #pragma unroll
        for (int ks = 0; ks < 2; ks++) {          // two k16 steps in BK=32
            uint32_t bh[2][4], bl[2][4];
            #pragma unroll
            for (int nb = 0; nb < 2; nb++) {
                const uint32_t b_addr = buf + (uint32_t)(OFF_BH + (wn * 32 + nb * 16) * ROWB + ks * 32) + boff;
                LDSM4(bh[nb], b_addr);
                LDSM4(bl[nb], b_addr + ARR_B);
            }
            #pragma unroll
            for (int mi = 0; mi < 4; mi++) {
                uint32_t ah[4], al[4];
                const uint32_t a_addr = buf + (uint32_t)((wm * 64 + mi * 16) * ROWB + ks * 32) + aoff;
                LDSM4(ah, a_addr);
                LDSM4(al, a_addr + ARR_B);
                // pass-outermost within mi: 4 distinct accumulators between reuse
                #pragma unroll
                for (int nb = 0; nb < 2; nb++)
                    #pragma unroll
                    for (int j = 0; j < 2; j++)
                        MMA_BF16(c[mi][nb * 2 + j], ah, bh[nb][2 * j], bh[nb][2 * j + 1]);
                #pragma unroll
                for (int nb = 0; nb < 2; nb++)
                    #pragma unroll
                    for (int j = 0; j < 2; j++)
                        MMA_BF16(c[mi][nb * 2 + j], ah, bl[nb][2 * j], bl[nb][2 * j + 1]);
                #pragma unroll
                for (int nb = 0; nb < 2; nb++)
                    #pragma unroll
                    for (int j = 0; j < 2; j++)
                        MMA_BF16(c[mi][nb * 2 + j], al, bh[nb][2 * j], bh[nb][2 * j + 1]);
            }
        }
        __syncthreads();   // all warps done with buf t before next iter overwrites it
    }

    // ---- epilogue: write C frags straight to g_res ----
    const int rbase = mBase + wm * 64 + (lane >> 2);
    const int cbase = nBase + wn * 32 + (lane & 3) * 2;
    #pragma unroll
    for (int mi = 0; mi < 4; mi++)
        #pragma unroll
        for (int ni = 0; ni < 4; ni++) {
            float* p = g_res + (size_t)(rbase + mi * 16) * SAMPLES + cbase + ni * 8;
            *(float2*)p                 = make_float2(c[mi][ni][0], c[mi][ni][1]);
            *(float2*)(p + 8 * SAMPLES) = make_float2(c[mi][ni][2], c[mi][ni][3]);
        }
    #undef LOAD_STAGE
}

// ---------------------------------------------------------------------------
// K3: fused per-frame norm + scale + overlap-add. One block (256 thr) per row.
//     Phase 1: warp-per-frame hann-weighted norms -> smem scales.
//     Phase 2: out[s] = res[s]*(hann[j]*sc[f1] + hann[j+256]*sc[f1-1]).
// ---------------------------------------------------------------------------
__global__ __launch_bounds__(256) void k_epilogue(float* __restrict__ out)
{
    __shared__ float hs[WIN];
    __shared__ float sc[N_FRAMES];
    const int r   = blockIdx.x;
    const int tid = threadIdx.x;
    const int w   = tid >> 5;
    const int l   = tid & 31;
    hs[tid] = g_hann[tid]; hs[tid + 256] = g_hann[tid + 256];
    __syncthreads();

    // phase 1: frame norms
    for (int f = w; f < N_FRAMES; f += 8) {
        float sum = 0.f;
        const int base = f * HOP + l * 16;
        #pragma unroll
        for (int j4 = 0; j4 < 4; j4++) {
            const int s = base + j4 * 4;
            if (s < SAMPLES) {
                float4 v = *(const float4*)(g_res + (size_t)r * SAMPLES + s);
                const int wp = l * 16 + j4 * 4;
                float a0 = v.x * hs[wp + 0], a1 = v.y * hs[wp + 1];
                float a2 = v.z * hs[wp + 2], a3 = v.w * hs[wp + 3];
                sum += a0 * a0 + a1 * a1 + a2 * a2 + a3 * a3;
            }
        }
        #pragma unroll
        for (int o = 16; o > 0; o >>= 1) sum += __shfl_down_sync(0xffffffffu, sum, o);
        if (l == 0)
            sc[f] = g_mom[r * N_FRAMES + f] / (sqrtf(sum) + 1e-8f);
    }
    __syncthreads();

    // phase 2: pointwise scale + OLA (row should be L1/L2-hot from phase 1)
    for (int s0 = tid * 4; s0 < SAMPLES; s0 += 1024) {
        const int f1 = s0 >> 8;
        const int j  = s0 & 255;
        const float g1 = sc[f1];
        const float g0 = (f1 > 0) ? sc[f1 - 1] : 0.f;
        float4 v = *(const float4*)(g_res + (size_t)r * SAMPLES + s0);
        float4 o;
        o.x = v.x * (hs[j + 0] * g1 + hs[j + 0 + HOP] * g0);
        o.y = v.y * (hs[j + 1] * g1 + hs[j + 1 + HOP] * g0);
        o.z = v.z * (hs[j + 2] * g1 + hs[j + 2 + HOP] * g0);
        o.w = v.w * (hs[j + 3] * g1 + hs[j + 3 + HOP] * g0);
        *(float4*)(out + (size_t)r * SAMPLES + s0) = o;
    }
}

// ---------------------------------------------------------------------------
extern "C" void kernel_launch(void* const* d_in, const int* in_sizes, int n_in,
                              void* d_out, int out_size)
{
    const float* x     = (const float*)d_in[0];
    const float* W_sel = (const float*)d_in[1];
    const float* b_sel = (const float*)d_in[2];
    const float* W_mom = (const float*)d_in[3];
    const float* b_mom = (const float*)d_in[4];
    const float* atoms = (const float*)d_in[5];

    float* out = (float*)d_out;
    const int audio_elems = R_ROWS * SAMPLES;
    const int write_mom = (out_size >= audio_elems + R_ROWS * N_FRAMES) ? 1 : 0;
    float* out_mom = out + audio_elems;

    cudaFuncSetAttribute(k_gemm, cudaFuncAttributeMaxDynamicSharedMemorySize, GEMM_SMEM);

    k_hann<<<1, WIN>>>();
    k_transpose<<<dim3(N_ATOMS / 64, SAMPLES / 64), 256>>>(atoms);
    k_sel_mom<<<R_ROWS, 256>>>(x, W_sel, b_sel, W_mom, b_mom, out_mom, write_mom);
    // grid.x = M tiles (8) fastest -> CTAs sharing an atoms N-strip run together (L2 reuse)
    k_gemm<<<dim3(R_ROWS / BM, SAMPLES / BN), 256, GEMM_SMEM>>>();
    k_epilogue<<<R_ROWS, 256>>>(out);
}

// round 9
// speedup vs baseline: 2.5267x; 1.0774x over previous
#include <cuda_runtime.h>
#include <cuda_bf16.h>
#include <math.h>
#include <stdint.h>

// Problem dims
#define R_ROWS   1024      // B*E = 16*64
#define LATENT   128
#define N_ATOMS  1024      // K of the big GEMM
#define N_FRAMES 128
#define SAMPLES  32768
#define WIN      512
#define HOP      256

// GEMM tiling: CTA 128x128, BK=32, 8 warps (warp tile 64x32), 2 CTAs/SM
// smem rows: 64 B (32 bf16), XOR-swizzled chunks -> no padding
#define BM 128
#define BN 128
#define BK 32
#define NT (N_ATOMS / BK)      // 32 k-tiles
#define ROWB   64              // bytes per smem row
#define ARR_B  (128 * ROWB)    // 8192 B per matrix
#define OFF_AH 0
#define OFF_AL (ARR_B)
#define OFF_BH (2 * ARR_B)
#define OFF_BL (3 * ARR_B)
#define STAGE_B (4 * ARR_B)    // 32768
#define NSTAGE 3
#define GEMM_SMEM (NSTAGE * STAGE_B)  // 98304 per CTA (x2 CTAs = 192K/SM)

// Scratch (static device globals — no runtime allocation allowed)
__device__ __nv_bfloat16 g_selh[R_ROWS * N_ATOMS];     // 2 MB
__device__ __nv_bfloat16 g_sell[R_ROWS * N_ATOMS];     // 2 MB
__device__ __nv_bfloat16 g_ath [SAMPLES * N_ATOMS];    // atoms^T hi  64 MB
__device__ __nv_bfloat16 g_atl [SAMPLES * N_ATOMS];    // atoms^T lo  64 MB
__device__ float g_res[R_ROWS * SAMPLES];              // 128 MB
__device__ float g_mom[R_ROWS * N_FRAMES];
__device__ float g_hann[WIN];

// ---------------------------------------------------------------------------
// low-level helpers (base-target sm_80+ instructions only)
// ---------------------------------------------------------------------------
__device__ __forceinline__ uint32_t smem_to_u32(const void* p) {
    uint32_t a;
    asm("{ .reg .u64 t; cvta.to.shared.u64 t, %1; cvt.u32.u64 %0, t; }" : "=r"(a) : "l"(p));
    return a;
}
#define CP_ASYNC16(dst, src) \
    asm volatile("cp.async.cg.shared.global [%0], [%1], 16;" :: "r"(dst), "l"(src))
#define CP_COMMIT()  asm volatile("cp.async.commit_group;" ::: "memory")
#define CP_WAIT1()   asm volatile("cp.async.wait_group 1;" ::: "memory")
#define CP_WAIT0()   asm volatile("cp.async.wait_group 0;" ::: "memory")

#define LDSM4(r, addr) \
    asm volatile("ldmatrix.sync.aligned.m8n8.x4.shared.b16 {%0,%1,%2,%3}, [%4];" \
        : "=r"((r)[0]), "=r"((r)[1]), "=r"((r)[2]), "=r"((r)[3]) : "r"(addr))

#define MMA_BF16(c, a, b0, b1) \
    asm volatile("mma.sync.aligned.m16n8k16.row.col.f32.bf16.bf16.f32 " \
        "{%0,%1,%2,%3},{%4,%5,%6,%7},{%8,%9},{%0,%1,%2,%3};" \
        : "+f"((c)[0]), "+f"((c)[1]), "+f"((c)[2]), "+f"((c)[3]) \
        : "r"((a)[0]), "r"((a)[1]), "r"((a)[2]), "r"((a)[3]), "r"(b0), "r"(b1))

// ---------------------------------------------------------------------------
// K0: hann window table (periodic)
// ---------------------------------------------------------------------------
__global__ void k_hann() {
    int w = threadIdx.x;
    if (w < WIN)
        g_hann[w] = 0.5f * (1.0f - cosf((float)(2.0 * 3.14159265358979323846 / (double)WIN) * (float)w));
}

// ---------------------------------------------------------------------------
// K_T: atoms [K=1024][S=32768] f32  ->  g_ath/g_atl [S][K] bf16 (split)
// ---------------------------------------------------------------------------
__global__ __launch_bounds__(256) void k_transpose(const float* __restrict__ atoms)
{
    __shared__ float ts[64][65];
    const int k0 = blockIdx.x * 64;
    const int n0 = blockIdx.y * 64;
    const int t  = threadIdx.x;

    {
        const int r = t >> 2, cs = (t & 3) * 16;
        const float4* src = (const float4*)(atoms + (size_t)(k0 + r) * SAMPLES + n0 + cs);
        #pragma unroll
        for (int j = 0; j < 4; j++) {
            float4 v = src[j];
            ts[r][cs + j * 4 + 0] = v.x; ts[r][cs + j * 4 + 1] = v.y;
            ts[r][cs + j * 4 + 2] = v.z; ts[r][cs + j * 4 + 3] = v.w;
        }
    }
    __syncthreads();
    {
        const int n = t >> 2, ks = (t & 3) * 16;
        uint32_t ph[8], pl[8];
        #pragma unroll
        for (int j = 0; j < 8; j++) {
            float v0 = ts[ks + 2 * j + 0][n];
            float v1 = ts[ks + 2 * j + 1][n];
            __nv_bfloat16 h0 = __float2bfloat16(v0);
            __nv_bfloat16 h1 = __float2bfloat16(v1);
            __nv_bfloat16 l0 = __float2bfloat16(v0 - __bfloat162float(h0));
            __nv_bfloat16 l1 = __float2bfloat16(v1 - __bfloat162float(h1));
            ph[j] = ((uint32_t)*(uint16_t*)&h0) | (((uint32_t)*(uint16_t*)&h1) << 16);
            pl[j] = ((uint32_t)*(uint16_t*)&l0) | (((uint32_t)*(uint16_t*)&l1) << 16);
        }
        uint4* dh = (uint4*)(g_ath + (size_t)(n0 + n) * N_ATOMS + k0 + ks);
        uint4* dl = (uint4*)(g_atl + (size_t)(n0 + n) * N_ATOMS + k0 + ks);
        dh[0] = make_uint4(ph[0], ph[1], ph[2], ph[3]);
        dh[1] = make_uint4(ph[4], ph[5], ph[6], ph[7]);
        dl[0] = make_uint4(pl[0], pl[1], pl[2], pl[3]);
        dl[1] = make_uint4(pl[4], pl[5], pl[6], pl[7]);
    }
}

// ---------------------------------------------------------------------------
// K1: per-row selection softmax (-> bf16 hi/lo) + momentum cumprod
// ---------------------------------------------------------------------------
__global__ __launch_bounds__(256) void k_sel_mom(
    const float* __restrict__ x,
    const float* __restrict__ W_sel, const float* __restrict__ b_sel,
    const float* __restrict__ W_mom, const float* __restrict__ b_mom,
    float* __restrict__ out_mom, int write_mom)
{
    __shared__ float xs[LATENT];
    __shared__ float red[256];
    __shared__ float lm[N_FRAMES];

    const int r   = blockIdx.x;
    const int tid = threadIdx.x;

    if (tid < LATENT) xs[tid] = x[r * LATENT + tid];
    __syncthreads();

    float z[4];
    #pragma unroll
    for (int i = 0; i < 4; i++) {
        const int a = tid + 256 * i;
        const float4* wp = (const float4*)(W_sel + a * LATENT);
        float acc = 0.f;
        #pragma unroll
        for (int l4 = 0; l4 < LATENT / 4; l4++) {
            float4 w4 = wp[l4];
            acc += xs[l4 * 4 + 0] * w4.x + xs[l4 * 4 + 1] * w4.y
                 + xs[l4 * 4 + 2] * w4.z + xs[l4 * 4 + 3] * w4.w;
        }
        z[i] = acc + b_sel[a];
    }

    float m = fmaxf(fmaxf(z[0], z[1]), fmaxf(z[2], z[3]));
    red[tid] = m; __syncthreads();
    for (int s = 128; s > 0; s >>= 1) { if (tid < s) red[tid] = fmaxf(red[tid], red[tid + s]); __syncthreads(); }
    m = red[0]; __syncthreads();

    float e[4], psum = 0.f;
    #pragma unroll
    for (int i = 0; i < 4; i++) { e[i] = expf(z[i] - m); psum += e[i]; }
    red[tid] = psum; __syncthreads();
    for (int s = 128; s > 0; s >>= 1) { if (tid < s) red[tid] += red[tid + s]; __syncthreads(); }
    const float inv = 1.0f / red[0];
    #pragma unroll
    for (int i = 0; i < 4; i++) {
        const float v = e[i] * inv;
        __nv_bfloat16 h = __float2bfloat16(v);
        __nv_bfloat16 l = __float2bfloat16(v - __bfloat162float(h));
        g_selh[r * N_ATOMS + tid + 256 * i] = h;
        g_sell[r * N_ATOMS + tid + 256 * i] = l;
    }

    if (tid < N_FRAMES) {
        const float4* wp = (const float4*)(W_mom + tid * LATENT);
        float acc = 0.f;
        #pragma unroll
        for (int l4 = 0; l4 < LATENT / 4; l4++) {
            float4 w4 = wp[l4];
            acc += xs[l4 * 4 + 0] * w4.x + xs[l4 * 4 + 1] * w4.y
                 + xs[l4 * 4 + 2] * w4.z + xs[l4 * 4 + 3] * w4.w;
        }
        acc += b_mom[tid];
        const float sg = 1.0f / (1.0f + expf(-acc));
        lm[tid] = logf(1e-12f + 0.2f + 0.72f * sg);
    }
    __syncthreads();
    if (tid == 0) {
        float c = 0.f;
        for (int f = 0; f < N_FRAMES; f++) {
            c += lm[f];
            const float mm = expf(c);
            g_mom[r * N_FRAMES + f] = mm;
            if (write_mom) out_mom[r * N_FRAMES + f] = mm;
        }
    }
}

// ---------------------------------------------------------------------------
// K2: res = sel @ atoms, warp HMMA, split-bf16 3-pass.
//     CTA 128x128, warp 64x32, 2 CTAs/SM, 3-stage cp.async, 1 sync/iter,
//     XOR-swizzled 64B smem rows (chunk ^= (row>>1)&3).
// ---------------------------------------------------------------------------
__global__ __launch_bounds__(256, 2) void k_gemm()
{
    extern __shared__ char sm_dyn[];
    const uint32_t smem_u = smem_to_u32(sm_dyn);

    const int tid  = threadIdx.x;
    const int wid  = tid >> 5;
    const int lane = tid & 31;
    const int wm   = wid & 1;        // 2 warps in M  (64 rows)
    const int wn   = wid >> 1;       // 4 warps in N  (32 cols)
    const int mBase = blockIdx.x * BM;
    const int nBase = blockIdx.y * BN;

    // ---- per-thread gmem->smem copy descriptors (8 x 16B per stage) ----
    // chunks: 0..511 Ah, 512..1023 Al, 1024..1535 Bh, 1536..2047 Bl
    const __nv_bfloat16* srcp[8];
    uint32_t dstoff[8];
    #pragma unroll
    for (int i = 0; i < 8; i++) {
        const int q   = tid + i * 256;
        const int arr = q >> 9;           // 0 Ah, 1 Al, 2 Bh, 3 Bl
        const int qq  = q & 511;
        const int row = qq >> 2;
        const int c   = qq & 3;
        const __nv_bfloat16* base =
            (arr == 0) ? g_selh : (arr == 1) ? g_sell : (arr == 2) ? g_ath : g_atl;
        const int grow = (arr < 2) ? (mBase + row) : (nBase + row);
        srcp[i]   = base + (size_t)grow * N_ATOMS + c * 8;
        const int cs = c ^ ((row >> 1) & 3);            // swizzled 16B chunk
        dstoff[i] = (uint32_t)(arr * ARR_B + row * ROWB + cs * 16);
    }

    #define LOAD_STAGE(buf, kc) do {                                     \
        const uint32_t sb_ = smem_u + (uint32_t)(buf) * STAGE_B;         \
        _Pragma("unroll")                                                \
        for (int i_ = 0; i_ < 8; i_++)                                   \
            CP_ASYNC16(sb_ + dstoff[i_], srcp[i_] + (kc));               \
        CP_COMMIT();                                                     \
    } while (0)

    // ---- ldmatrix lane geometry (swizzle depends only on local row) ----
    const int a_lr   = lane & 15;             // local row within 16-row frag
    const int a_jb   = lane >> 4;             // base chunk parity
    const int a_sw   = (a_lr >> 1) & 3;
    const uint32_t a_rowoff = (uint32_t)(a_lr * ROWB);
    const int b_lr   = ((lane >> 4) * 8) + (lane & 7);
    const int b_jb   = (lane >> 3) & 1;
    const int b_sw   = (b_lr >> 1) & 3;
    const uint32_t b_rowoff = (uint32_t)(b_lr * ROWB);

    float c[4][4][4];
    #pragma unroll
    for (int mi = 0; mi < 4; mi++)
        #pragma unroll
        for (int ni = 0; ni < 4; ni++)
            #pragma unroll
            for (int k = 0; k < 4; k++) c[mi][ni][k] = 0.f;

    LOAD_STAGE(0, 0);
    LOAD_STAGE(1, BK);

    for (int t = 0; t < NT; t++) {
        if (t == NT - 1) { CP_WAIT0(); } else { CP_WAIT1(); }
        __syncthreads();
        if (t + 2 < NT) LOAD_STAGE((t + 2) % NSTAGE, (t + 2) * BK);

        const uint32_t buf = smem_u + (uint32_t)(t % NSTAGE) * STAGE_B;

        #pragma unroll
        for (int ks = 0; ks < 2; ks++) {          // two k16 steps in BK=32
            const uint32_t a_ch = (uint32_t)(((ks * 2 + a_jb) ^ a_sw) * 16);
            const uint32_t b_ch = (uint32_t)(((ks * 2 + b_jb) ^ b_sw) * 16);

            uint32_t bh[2][4], bl[2][4];
            #pragma unroll
            for (int nb = 0; nb < 2; nb++) {
                const uint32_t b_addr = buf + (uint32_t)(OFF_BH + (wn * 32 + nb * 16) * ROWB)
                                      + b_rowoff + b_ch;
                LDSM4(bh[nb], b_addr);
                LDSM4(bl[nb], b_addr + ARR_B);
            }
            #pragma unroll
            for (int mi = 0; mi < 4; mi++) {
                uint32_t ah[4], al[4];
                const uint32_t a_addr = buf + (uint32_t)((wm * 64 + mi * 16) * ROWB)
                                      + a_rowoff + a_ch;
                LDSM4(ah, a_addr);
                LDSM4(al, a_addr + ARR_B);
                #pragma unroll
                for (int nb = 0; nb < 2; nb++)
                    #pragma unroll
                    for (int j = 0; j < 2; j++)
                        MMA_BF16(c[mi][nb * 2 + j], ah, bh[nb][2 * j], bh[nb][2 * j + 1]);
                #pragma unroll
                for (int nb = 0; nb < 2; nb++)
                    #pragma unroll
                    for (int j = 0; j < 2; j++)
                        MMA_BF16(c[mi][nb * 2 + j], ah, bl[nb][2 * j], bl[nb][2 * j + 1]);
                #pragma unroll
                for (int nb = 0; nb < 2; nb++)
                    #pragma unroll
                    for (int j = 0; j < 2; j++)
                        MMA_BF16(c[mi][nb * 2 + j], al, bh[nb][2 * j], bh[nb][2 * j + 1]);
            }
        }
    }

    // ---- epilogue: write C frags straight to g_res ----
    const int rbase = mBase + wm * 64 + (lane >> 2);
    const int cbase = nBase + wn * 32 + (lane & 3) * 2;
    #pragma unroll
    for (int mi = 0; mi < 4; mi++)
        #pragma unroll
        for (int ni = 0; ni < 4; ni++) {
            float* p = g_res + (size_t)(rbase + mi * 16) * SAMPLES + cbase + ni * 8;
            *(float2*)p                 = make_float2(c[mi][ni][0], c[mi][ni][1]);
            *(float2*)(p + 8 * SAMPLES) = make_float2(c[mi][ni][2], c[mi][ni][3]);
        }
    #undef LOAD_STAGE
}

// ---------------------------------------------------------------------------
// K3: fused per-frame norm + scale + overlap-add. One block (256 thr) per row.
// ---------------------------------------------------------------------------
__global__ __launch_bounds__(256) void k_epilogue(float* __restrict__ out)
{
    __shared__ float hs[WIN];
    __shared__ float sc[N_FRAMES];
    const int r   = blockIdx.x;
    const int tid = threadIdx.x;
    const int w   = tid >> 5;
    const int l   = tid & 31;
    hs[tid] = g_hann[tid]; hs[tid + 256] = g_hann[tid + 256];
    __syncthreads();

    // phase 1: frame norms
    for (int f = w; f < N_FRAMES; f += 8) {
        float sum = 0.f;
        const int base = f * HOP + l * 16;
        #pragma unroll
        for (int j4 = 0; j4 < 4; j4++) {
            const int s = base + j4 * 4;
            if (s < SAMPLES) {
                float4 v = *(const float4*)(g_res + (size_t)r * SAMPLES + s);
                const int wp = l * 16 + j4 * 4;
                float a0 = v.x * hs[wp + 0], a1 = v.y * hs[wp + 1];
                float a2 = v.z * hs[wp + 2], a3 = v.w * hs[wp + 3];
                sum += a0 * a0 + a1 * a1 + a2 * a2 + a3 * a3;
            }
        }
        #pragma unroll
        for (int o = 16; o > 0; o >>= 1) sum += __shfl_down_sync(0xffffffffu, sum, o);
        if (l == 0)
            sc[f] = g_mom[r * N_FRAMES + f] / (sqrtf(sum) + 1e-8f);
    }
    __syncthreads();

    // phase 2: pointwise scale + OLA
    for (int s0 = tid * 4; s0 < SAMPLES; s0 += 1024) {
        const int f1 = s0 >> 8;
        const int j  = s0 & 255;
        const float g1 = sc[f1];
        const float g0 = (f1 > 0) ? sc[f1 - 1] : 0.f;
        float4 v = *(const float4*)(g_res + (size_t)r * SAMPLES + s0);
        float4 o;
        o.x = v.x * (hs[j + 0] * g1 + hs[j + 0 + HOP] * g0);
        o.y = v.y * (hs[j + 1] * g1 + hs[j + 1 + HOP] * g0);
        o.z = v.z * (hs[j + 2] * g1 + hs[j + 2 + HOP] * g0);
        o.w = v.w * (hs[j + 3] * g1 + hs[j + 3 + HOP] * g0);
        *(float4*)(out + (size_t)r * SAMPLES + s0) = o;
    }
}

// ---------------------------------------------------------------------------
extern "C" void kernel_launch(void* const* d_in, const int* in_sizes, int n_in,
                              void* d_out, int out_size)
{
    const float* x     = (const float*)d_in[0];
    const float* W_sel = (const float*)d_in[1];
    const float* b_sel = (const float*)d_in[2];
    const float* W_mom = (const float*)d_in[3];
    const float* b_mom = (const float*)d_in[4];
    const float* atoms = (const float*)d_in[5];

    float* out = (float*)d_out;
    const int audio_elems = R_ROWS * SAMPLES;
    const int write_mom = (out_size >= audio_elems + R_ROWS * N_FRAMES) ? 1 : 0;
    float* out_mom = out + audio_elems;

    cudaFuncSetAttribute(k_gemm, cudaFuncAttributeMaxDynamicSharedMemorySize, GEMM_SMEM);

    k_hann<<<1, WIN>>>();
    k_transpose<<<dim3(N_ATOMS / 64, SAMPLES / 64), 256>>>(atoms);
    k_sel_mom<<<R_ROWS, 256>>>(x, W_sel, b_sel, W_mom, b_mom, out_mom, write_mom);
    // grid.x = M tiles (8) fastest -> CTAs sharing an atoms N-strip run together (L2 reuse)
    k_gemm<<<dim3(R_ROWS / BM, SAMPLES / BN), 256, GEMM_SMEM>>>();
    k_epilogue<<<R_ROWS, 256>>>(out);
}

// round 11
// speedup vs baseline: 3.2729x; 1.2953x over previous
#include <cuda_runtime.h>
#include <cuda_fp16.h>
#include <math.h>
#include <stdint.h>

// Problem dims
#define R_ROWS   1024      // B*E = 16*64
#define LATENT   128
#define N_ATOMS  1024      // K of the big GEMM
#define N_FRAMES 128
#define SAMPLES  32768
#define WIN      512
#define HOP      256

#define ATOM_SCALE 64.0f   // pipeline is scale-invariant in res; lifts fp16 lo out of subnormals

// GEMM tiling: CTA 128x128, BK=32, 8 warps (warp tile 64x32), 2 CTAs/SM
// smem rows: 64 B (32 fp16), XOR-swizzled chunks -> no padding
#define BM 128
#define BN 128
#define BK 32
#define NT (N_ATOMS / BK)      // 32 k-tiles
#define ROWB   64              // bytes per smem row
#define ARR_B  (128 * ROWB)    // 8192 B per matrix
#define OFF_A  0
#define OFF_BH (ARR_B)
#define OFF_BL (2 * ARR_B)
#define STAGE_B (3 * ARR_B)    // 24576
#define NSTAGE 4
#define GEMM_SMEM (NSTAGE * STAGE_B)  // 98304 per CTA (x2 CTAs = 192K/SM)

// Scratch (static device globals — no runtime allocation allowed)
__device__ __half g_selh[R_ROWS * N_ATOMS];     // 2 MB (fp16, no split needed)
__device__ __half g_ath [SAMPLES * N_ATOMS];    // (64*atoms)^T hi  64 MB
__device__ __half g_atl [SAMPLES * N_ATOMS];    // (64*atoms)^T lo  64 MB
__device__ float g_res[R_ROWS * SAMPLES];       // 128 MB (scaled by 64)
__device__ float g_mom[R_ROWS * N_FRAMES];
__device__ float g_hann[WIN];

// ---------------------------------------------------------------------------
// low-level helpers (base-target sm_80+ instructions only)
// ---------------------------------------------------------------------------
__device__ __forceinline__ uint32_t smem_to_u32(const void* p) {
    uint32_t a;
    asm("{ .reg .u64 t; cvta.to.shared.u64 t, %1; cvt.u32.u64 %0, t; }" : "=r"(a) : "l"(p));
    return a;
}
#define CP_ASYNC16(dst, src) \
    asm volatile("cp.async.cg.shared.global [%0], [%1], 16;" :: "r"(dst), "l"(src))
#define CP_COMMIT()  asm volatile("cp.async.commit_group;" ::: "memory")
#define CP_WAIT2()   asm volatile("cp.async.wait_group 2;" ::: "memory")

#define LDSM4(r, addr) \
    asm volatile("ldmatrix.sync.aligned.m8n8.x4.shared.b16 {%0,%1,%2,%3}, [%4];" \
        : "=r"((r)[0]), "=r"((r)[1]), "=r"((r)[2]), "=r"((r)[3]) : "r"(addr))

#define MMA_F16(c, a, b0, b1) \
    asm volatile("mma.sync.aligned.m16n8k16.row.col.f32.f16.f16.f32 " \
        "{%0,%1,%2,%3},{%4,%5,%6,%7},{%8,%9},{%0,%1,%2,%3};" \
        : "+f"((c)[0]), "+f"((c)[1]), "+f"((c)[2]), "+f"((c)[3]) \
        : "r"((a)[0]), "r"((a)[1]), "r"((a)[2]), "r"((a)[3]), "r"(b0), "r"(b1))

// ---------------------------------------------------------------------------
// K0: hann window table (periodic)
// ---------------------------------------------------------------------------
__global__ void k_hann() {
    int w = threadIdx.x;
    if (w < WIN)
        g_hann[w] = 0.5f * (1.0f - cosf((float)(2.0 * 3.14159265358979323846 / (double)WIN) * (float)w));
}

// ---------------------------------------------------------------------------
// K_T: atoms [K=1024][S=32768] f32 -> g_ath/g_atl [S][K] fp16 (scaled, split)
// ---------------------------------------------------------------------------
__global__ __launch_bounds__(256) void k_transpose(const float* __restrict__ atoms)
{
    __shared__ float ts[64][65];
    const int k0 = blockIdx.x * 64;
    const int n0 = blockIdx.y * 64;
    const int t  = threadIdx.x;

    {
        const int r = t >> 2, cs = (t & 3) * 16;
        const float4* src = (const float4*)(atoms + (size_t)(k0 + r) * SAMPLES + n0 + cs);
        #pragma unroll
        for (int j = 0; j < 4; j++) {
            float4 v = src[j];
            ts[r][cs + j * 4 + 0] = v.x; ts[r][cs + j * 4 + 1] = v.y;
            ts[r][cs + j * 4 + 2] = v.z; ts[r][cs + j * 4 + 3] = v.w;
        }
    }
    __syncthreads();
    {
        const int n = t >> 2, ks = (t & 3) * 16;
        uint32_t ph[8], pl[8];
        #pragma unroll
        for (int j = 0; j < 8; j++) {
            float v0 = ts[ks + 2 * j + 0][n] * ATOM_SCALE;
            float v1 = ts[ks + 2 * j + 1][n] * ATOM_SCALE;
            __half h0 = __float2half(v0);
            __half h1 = __float2half(v1);
            __half l0 = __float2half(v0 - __half2float(h0));
            __half l1 = __float2half(v1 - __half2float(h1));
            ph[j] = ((uint32_t)__half_as_ushort(h0)) | (((uint32_t)__half_as_ushort(h1)) << 16);
            pl[j] = ((uint32_t)__half_as_ushort(l0)) | (((uint32_t)__half_as_ushort(l1)) << 16);
        }
        uint4* dh = (uint4*)(g_ath + (size_t)(n0 + n) * N_ATOMS + k0 + ks);
        uint4* dl = (uint4*)(g_atl + (size_t)(n0 + n) * N_ATOMS + k0 + ks);
        dh[0] = make_uint4(ph[0], ph[1], ph[2], ph[3]);
        dh[1] = make_uint4(ph[4], ph[5], ph[6], ph[7]);
        dl[0] = make_uint4(pl[0], pl[1], pl[2], pl[3]);
        dl[1] = make_uint4(pl[4], pl[5], pl[6], pl[7]);
    }
}

// ---------------------------------------------------------------------------
// K1: per-row selection softmax (-> fp16) + momentum cumprod
// ---------------------------------------------------------------------------
__global__ __launch_bounds__(256) void k_sel_mom(
    const float* __restrict__ x,
    const float* __restrict__ W_sel, const float* __restrict__ b_sel,
    const float* __restrict__ W_mom, const float* __restrict__ b_mom,
    float* __restrict__ out_mom, int write_mom)
{
    __shared__ float xs[LATENT];
    __shared__ float red[256];
    __shared__ float lm[N_FRAMES];

    const int r   = blockIdx.x;
    const int tid = threadIdx.x;

    if (tid < LATENT) xs[tid] = x[r * LATENT + tid];
    __syncthreads();

    float z[4];
    #pragma unroll
    for (int i = 0; i < 4; i++) {
        const int a = tid + 256 * i;
        const float4* wp = (const float4*)(W_sel + a * LATENT);
        float acc = 0.f;
        #pragma unroll
        for (int l4 = 0; l4 < LATENT / 4; l4++) {
            float4 w4 = wp[l4];
            acc += xs[l4 * 4 + 0] * w4.x + xs[l4 * 4 + 1] * w4.y
                 + xs[l4 * 4 + 2] * w4.z + xs[l4 * 4 + 3] * w4.w;
        }
        z[i] = acc + b_sel[a];
    }

    float m = fmaxf(fmaxf(z[0], z[1]), fmaxf(z[2], z[3]));
    red[tid] = m; __syncthreads();
    for (int s = 128; s > 0; s >>= 1) { if (tid < s) red[tid] = fmaxf(red[tid], red[tid + s]); __syncthreads(); }
    m = red[0]; __syncthreads();

    float e[4], psum = 0.f;
    #pragma unroll
    for (int i = 0; i < 4; i++) { e[i] = expf(z[i] - m); psum += e[i]; }
    red[tid] = psum; __syncthreads();
    for (int s = 128; s > 0; s >>= 1) { if (tid < s) red[tid] += red[tid + s]; __syncthreads(); }
    const float inv = 1.0f / red[0];
    #pragma unroll
    for (int i = 0; i < 4; i++)
        g_selh[r * N_ATOMS + tid + 256 * i] = __float2half(e[i] * inv);

    if (tid < N_FRAMES) {
        const float4* wp = (const float4*)(W_mom + tid * LATENT);
        float acc = 0.f;
        #pragma unroll
        for (int l4 = 0; l4 < LATENT / 4; l4++) {
            float4 w4 = wp[l4];
            acc += xs[l4 * 4 + 0] * w4.x + xs[l4 * 4 + 1] * w4.y
                 + xs[l4 * 4 + 2] * w4.z + xs[l4 * 4 + 3] * w4.w;
        }
        acc += b_mom[tid];
        const float sg = 1.0f / (1.0f + expf(-acc));
        lm[tid] = logf(1e-12f + 0.2f + 0.72f * sg);
    }
    __syncthreads();
    if (tid == 0) {
        float c = 0.f;
        for (int f = 0; f < N_FRAMES; f++) {
            c += lm[f];
            const float mm = expf(c);
            g_mom[r * N_FRAMES + f] = mm;
            if (write_mom) out_mom[r * N_FRAMES + f] = mm;
        }
    }
}

// ---------------------------------------------------------------------------
// K2: res = sel @ (64*atoms), warp HMMA fp16 2-pass (A*Bh + A*Bl).
//     CTA 128x128, warp 64x32, 2 CTAs/SM, 4-stage cp.async, 1 sync/iter,
//     XOR-swizzled 64B smem rows (chunk ^= (row>>1)&3).
// ---------------------------------------------------------------------------
__global__ __launch_bounds__(256, 2) void k_gemm()
{
    extern __shared__ char sm_dyn[];
    const uint32_t smem_u = smem_to_u32(sm_dyn);

    const int tid  = threadIdx.x;
    const int wid  = tid >> 5;
    const int lane = tid & 31;
    const int wm   = wid & 1;        // 2 warps in M  (64 rows)
    const int wn   = wid >> 1;       // 4 warps in N  (32 cols)
    const int mBase = blockIdx.x * BM;
    const int nBase = blockIdx.y * BN;

    // ---- per-thread gmem->smem copy descriptors (6 x 16B per stage) ----
    // chunks: 0..511 A, 512..1023 Bh, 1024..1535 Bl
    const __half* srcp[6];
    uint32_t dstoff[6];
    #pragma unroll
    for (int i = 0; i < 6; i++) {
        const int q   = tid + i * 256;
        const int arr = q >> 9;           // 0 A, 1 Bh, 2 Bl
        const int qq  = q & 511;
        const int row = qq >> 2;
        const int c   = qq & 3;
        const __half* base = (arr == 0) ? g_selh : (arr == 1) ? g_ath : g_atl;
        const int grow = (arr == 0) ? (mBase + row) : (nBase + row);
        srcp[i]   = base + (size_t)grow * N_ATOMS + c * 8;
        const int cs = c ^ ((row >> 1) & 3);            // swizzled 16B chunk
        dstoff[i] = (uint32_t)(arr * ARR_B + row * ROWB + cs * 16);
    }

    #define LOAD_STAGE(buf, kc) do {                                     \
        const uint32_t sb_ = smem_u + (uint32_t)(buf) * STAGE_B;         \
        _Pragma("unroll")                                                \
        for (int i_ = 0; i_ < 6; i_++)                                   \
            CP_ASYNC16(sb_ + dstoff[i_], srcp[i_] + (kc));               \
        CP_COMMIT();                                                     \
    } while (0)

    // ---- ldmatrix lane geometry (swizzle depends only on local row) ----
    const int a_lr   = lane & 15;             // local row within 16-row frag
    const int a_jb   = lane >> 4;             // base chunk parity
    const int a_sw   = (a_lr >> 1) & 3;
    const uint32_t a_rowoff = (uint32_t)(a_lr * ROWB);
    const int b_lr   = ((lane >> 4) * 8) + (lane & 7);
    const int b_jb   = (lane >> 3) & 1;
    const int b_sw   = (b_lr >> 1) & 3;
    const uint32_t b_rowoff = (uint32_t)(b_lr * ROWB);

    float c[4][4][4];
    #pragma unroll
    for (int mi = 0; mi < 4; mi++)
        #pragma unroll
        for (int ni = 0; ni < 4; ni++)
            #pragma unroll
            for (int k = 0; k < 4; k++) c[mi][ni][k] = 0.f;

    LOAD_STAGE(0, 0);
    LOAD_STAGE(1, BK);
    LOAD_STAGE(2, 2 * BK);

    for (int t = 0; t < NT; t++) {
        CP_WAIT2();                     // loads for t+1, t+2 may stay pending
        __syncthreads();
        if (t + 3 < NT) LOAD_STAGE((t + 3) % NSTAGE, (t + 3) * BK);

        const uint32_t buf = smem_u + (uint32_t)(t % NSTAGE) * STAGE_B;

        #pragma unroll
        for (int ks = 0; ks < 2; ks++) {          // two k16 steps in BK=32
            const uint32_t a_ch = (uint32_t)(((ks * 2 + a_jb) ^ a_sw) * 16);
            const uint32_t b_ch = (uint32_t)(((ks * 2 + b_jb) ^ b_sw) * 16);

            uint32_t bh[2][4], bl[2][4];
            #pragma unroll
            for (int nb = 0; nb < 2; nb++) {
                const uint32_t b_addr = buf + (uint32_t)(OFF_BH + (wn * 32 + nb * 16) * ROWB)
                                      + b_rowoff + b_ch;
                LDSM4(bh[nb], b_addr);
                LDSM4(bl[nb], b_addr + ARR_B);
            }
            #pragma unroll
            for (int mi = 0; mi < 4; mi++) {
                uint32_t ah[4];
                const uint32_t a_addr = buf + (uint32_t)((wm * 64 + mi * 16) * ROWB)
                                      + a_rowoff + a_ch;
                LDSM4(ah, a_addr);
                #pragma unroll
                for (int nb = 0; nb < 2; nb++)
                    #pragma unroll
                    for (int j = 0; j < 2; j++)
                        MMA_F16(c[mi][nb * 2 + j], ah, bh[nb][2 * j], bh[nb][2 * j + 1]);
                #pragma unroll
                for (int nb = 0; nb < 2; nb++)
                    #pragma unroll
                    for (int j = 0; j < 2; j++)
                        MMA_F16(c[mi][nb * 2 + j], ah, bl[nb][2 * j], bl[nb][2 * j + 1]);
            }
        }
    }

    // ---- epilogue: write C frags straight to g_res ----
    const int rbase = mBase + wm * 64 + (lane >> 2);
    const int cbase = nBase + wn * 32 + (lane & 3) * 2;
    #pragma unroll
    for (int mi = 0; mi < 4; mi++)
        #pragma unroll
        for (int ni = 0; ni < 4; ni++) {
            float* p = g_res + (size_t)(rbase + mi * 16) * SAMPLES + cbase + ni * 8;
            *(float2*)p                 = make_float2(c[mi][ni][0], c[mi][ni][1]);
            *(float2*)(p + 8 * SAMPLES) = make_float2(c[mi][ni][2], c[mi][ni][3]);
        }
    #undef LOAD_STAGE
}

// ---------------------------------------------------------------------------
// K3: fused per-frame norm + scale + overlap-add. One block (256 thr) per row.
//     Phase 1: per-256-block partials T1/T2 (each sample read ONCE);
//              norm^2[f] = T1[f] + T2[f+1].
//     Phase 2: out[s] = res[s]*(hann[j]*sc[f1] + hann[j+256]*sc[f1-1]).
//     (res is scaled by 64; frames/norm is scale-invariant so no correction.)
// ---------------------------------------------------------------------------
__global__ __launch_bounds__(256) void k_epilogue(float* __restrict__ out)
{
    __shared__ float hs[WIN];
    __shared__ float t1[N_FRAMES];
    __shared__ float t2[N_FRAMES];
    __shared__ float sc[N_FRAMES];
    const int r   = blockIdx.x;
    const int tid = threadIdx.x;
    const int w   = tid >> 5;
    const int l   = tid & 31;
    hs[tid] = g_hann[tid]; hs[tid + 256] = g_hann[tid + 256];
    __syncthreads();

    // phase 1: per-block partial sums, one read per sample
    for (int b = w; b < N_FRAMES; b += 8) {
        float s1 = 0.f, s2 = 0.f;
        const int base = b * HOP + l * 8;
        #pragma unroll
        for (int j4 = 0; j4 < 2; j4++) {
            const int s = base + j4 * 4;
            float4 v = *(const float4*)(g_res + (size_t)r * SAMPLES + s);
            const int i = l * 8 + j4 * 4;
            float a0 = v.x * hs[i + 0],       a1 = v.y * hs[i + 1];
            float a2 = v.z * hs[i + 2],       a3 = v.w * hs[i + 3];
            float b0 = v.x * hs[i + 0 + HOP], b1 = v.y * hs[i + 1 + HOP];
            float b2 = v.z * hs[i + 2 + HOP], b3 = v.w * hs[i + 3 + HOP];
            s1 += a0 * a0 + a1 * a1 + a2 * a2 + a3 * a3;
            s2 += b0 * b0 + b1 * b1 + b2 * b2 + b3 * b3;
        }
        #pragma unroll
        for (int o = 16; o > 0; o >>= 1) {
            s1 += __shfl_down_sync(0xffffffffu, s1, o);
            s2 += __shfl_down_sync(0xffffffffu, s2, o);
        }
        if (l == 0) { t1[b] = s1; t2[b] = s2; }
    }
    __syncthreads();
    if (tid < N_FRAMES) {
        const float n2 = t1[tid] + ((tid + 1 < N_FRAMES) ? t2[tid + 1] : 0.f);
        sc[tid] = g_mom[r * N_FRAMES + tid] / (sqrtf(n2) + 1e-8f);
    }
    __syncthreads();

    // phase 2: pointwise scale + OLA
    for (int s0 = tid * 4; s0 < SAMPLES; s0 += 1024) {
        const int f1 = s0 >> 8;
        const int j  = s0 & 255;
        const float g1 = sc[f1];
        const float g0 = (f1 > 0) ? sc[f1 - 1] : 0.f;
        float4 v = *(const float4*)(g_res + (size_t)r * SAMPLES + s0);
        float4 o;
        o.x = v.x * (hs[j + 0] * g1 + hs[j + 0 + HOP] * g0);
        o.y = v.y * (hs[j + 1] * g1 + hs[j + 1 + HOP] * g0);
        o.z = v.z * (hs[j + 2] * g1 + hs[j + 2 + HOP] * g0);
        o.w = v.w * (hs[j + 3] * g1 + hs[j + 3 + HOP] * g0);
        *(float4*)(out + (size_t)r * SAMPLES + s0) = o;
    }
}

// ---------------------------------------------------------------------------
extern "C" void kernel_launch(void* const* d_in, const int* in_sizes, int n_in,
                              void* d_out, int out_size)
{
    const float* x     = (const float*)d_in[0];
    const float* W_sel = (const float*)d_in[1];
    const float* b_sel = (const float*)d_in[2];
    const float* W_mom = (const float*)d_in[3];
    const float* b_mom = (const float*)d_in[4];
    const float* atoms = (const float*)d_in[5];

    float* out = (float*)d_out;
    const int audio_elems = R_ROWS * SAMPLES;
    const int write_mom = (out_size >= audio_elems + R_ROWS * N_FRAMES) ? 1 : 0;
    float* out_mom = out + audio_elems;

    cudaFuncSetAttribute(k_gemm, cudaFuncAttributeMaxDynamicSharedMemorySize, GEMM_SMEM);

    k_hann<<<1, WIN>>>();
    k_transpose<<<dim3(N_ATOMS / 64, SAMPLES / 64), 256>>>(atoms);
    k_sel_mom<<<R_ROWS, 256>>>(x, W_sel, b_sel, W_mom, b_mom, out_mom, write_mom);
    // grid.x = M tiles (8) fastest -> CTAs sharing an atoms N-strip run together (L2 reuse)
    k_gemm<<<dim3(R_ROWS / BM, SAMPLES / BN), 256, GEMM_SMEM>>>();
    k_epilogue<<<R_ROWS, 256>>>(out);
}

// round 12
// speedup vs baseline: 4.5379x; 1.3865x over previous
#include <cuda_runtime.h>
#include <cuda_fp16.h>
#include <math.h>
#include <stdint.h>

// Problem dims
#define R_ROWS   1024      // B*E = 16*64
#define LATENT   128
#define N_ATOMS  1024      // K of the big GEMM
#define N_FRAMES 128
#define SAMPLES  32768
#define WIN      512
#define HOP      256

// GEMM tiling: CTA 128x128, BK=32, 8 warps (warp tile 64x32), 2 CTAs/SM
// A smem: [M=128][K=32] fp16, 64B rows, XOR swizzle (chunk ^= (row>>1)&3)
// B smem: [K=32][N=128] fp16, 256B rows, XOR swizzle (chunk ^= row&7)
#define BM 128
#define BN 128
#define BK 32
#define NT (N_ATOMS / BK)      // 32 k-tiles
#define A_ROWB 64
#define B_ROWB 256
#define OFF_A  0
#define A_B    (128 * A_ROWB)            // 8192
#define OFF_B  (A_B)
#define B_B    (BK * B_ROWB)             // 8192
#define STAGE_B (A_B + B_B)              // 16384
#define NSTAGE 6
#define GEMM_SMEM (NSTAGE * STAGE_B)     // 98304 per CTA

// Scratch (static device globals — no runtime allocation allowed)
__device__ __half g_selh[R_ROWS * N_ATOMS];     // 2 MB (fp16 softmax weights)
__device__ __half g_ath [N_ATOMS * SAMPLES];    // atoms fp16, [K][N] native  64 MB
__device__ float g_res[R_ROWS * SAMPLES];       // 128 MB
__device__ float g_p1[R_ROWS * 2 * N_FRAMES];   // per-(row,block,half) hann1^2 partials 1 MB
__device__ float g_p2[R_ROWS * 2 * N_FRAMES];   // hann2^2 partials
__device__ float g_mom[R_ROWS * N_FRAMES];
__device__ float g_hann[WIN];

// ---------------------------------------------------------------------------
// low-level helpers (base-target sm_80+ instructions only)
// ---------------------------------------------------------------------------
__device__ __forceinline__ uint32_t smem_to_u32(const void* p) {
    uint32_t a;
    asm("{ .reg .u64 t; cvta.to.shared.u64 t, %1; cvt.u32.u64 %0, t; }" : "=r"(a) : "l"(p));
    return a;
}
#define CP_ASYNC16(dst, src) \
    asm volatile("cp.async.cg.shared.global [%0], [%1], 16;" :: "r"(dst), "l"(src))
#define CP_COMMIT()  asm volatile("cp.async.commit_group;" ::: "memory")
#define CP_WAIT4()   asm volatile("cp.async.wait_group 4;" ::: "memory")

#define LDSM4(r, addr) \
    asm volatile("ldmatrix.sync.aligned.m8n8.x4.shared.b16 {%0,%1,%2,%3}, [%4];" \
        : "=r"((r)[0]), "=r"((r)[1]), "=r"((r)[2]), "=r"((r)[3]) : "r"(addr))
#define LDSM4T(r, addr) \
    asm volatile("ldmatrix.sync.aligned.m8n8.x4.trans.shared.b16 {%0,%1,%2,%3}, [%4];" \
        : "=r"((r)[0]), "=r"((r)[1]), "=r"((r)[2]), "=r"((r)[3]) : "r"(addr))

#define MMA_F16(c, a, b0, b1) \
    asm volatile("mma.sync.aligned.m16n8k16.row.col.f32.f16.f16.f32 " \
        "{%0,%1,%2,%3},{%4,%5,%6,%7},{%8,%9},{%0,%1,%2,%3};" \
        : "+f"((c)[0]), "+f"((c)[1]), "+f"((c)[2]), "+f"((c)[3]) \
        : "r"((a)[0]), "r"((a)[1]), "r"((a)[2]), "r"((a)[3]), "r"(b0), "r"(b1))

// ---------------------------------------------------------------------------
// K0: hann window table (periodic)
// ---------------------------------------------------------------------------
__global__ void k_hann() {
    int w = threadIdx.x;
    if (w < WIN)
        g_hann[w] = 0.5f * (1.0f - cosf((float)(2.0 * 3.14159265358979323846 / (double)WIN) * (float)w));
}

// ---------------------------------------------------------------------------
// K_C: atoms f32 [K][S] -> fp16 [K][S] (pure streaming convert, no transpose)
// ---------------------------------------------------------------------------
__global__ __launch_bounds__(256) void k_tofp16(const float* __restrict__ atoms)
{
    const size_t total4 = (size_t)N_ATOMS * SAMPLES / 4;
    for (size_t i = (size_t)blockIdx.x * 256 + threadIdx.x; i < total4;
         i += (size_t)gridDim.x * 256) {
        float4 v = ((const float4*)atoms)[i];
        __half2 h0 = __floats2half2_rn(v.x, v.y);
        __half2 h1 = __floats2half2_rn(v.z, v.w);
        ((uint2*)g_ath)[i] = make_uint2(*(uint32_t*)&h0, *(uint32_t*)&h1);
    }
}

// ---------------------------------------------------------------------------
// K1: per-row selection softmax (-> fp16) + momentum cumprod
// ---------------------------------------------------------------------------
__global__ __launch_bounds__(256) void k_sel_mom(
    const float* __restrict__ x,
    const float* __restrict__ W_sel, const float* __restrict__ b_sel,
    const float* __restrict__ W_mom, const float* __restrict__ b_mom,
    float* __restrict__ out_mom, int write_mom)
{
    __shared__ float xs[LATENT];
    __shared__ float red[256];
    __shared__ float lm[N_FRAMES];

    const int r   = blockIdx.x;
    const int tid = threadIdx.x;

    if (tid < LATENT) xs[tid] = x[r * LATENT + tid];
    __syncthreads();

    float z[4];
    #pragma unroll
    for (int i = 0; i < 4; i++) {
        const int a = tid + 256 * i;
        const float4* wp = (const float4*)(W_sel + a * LATENT);
        float acc = 0.f;
        #pragma unroll
        for (int l4 = 0; l4 < LATENT / 4; l4++) {
            float4 w4 = wp[l4];
            acc += xs[l4 * 4 + 0] * w4.x + xs[l4 * 4 + 1] * w4.y
                 + xs[l4 * 4 + 2] * w4.z + xs[l4 * 4 + 3] * w4.w;
        }
        z[i] = acc + b_sel[a];
    }

    float m = fmaxf(fmaxf(z[0], z[1]), fmaxf(z[2], z[3]));
    red[tid] = m; __syncthreads();
    for (int s = 128; s > 0; s >>= 1) { if (tid < s) red[tid] = fmaxf(red[tid], red[tid + s]); __syncthreads(); }
    m = red[0]; __syncthreads();

    float e[4], psum = 0.f;
    #pragma unroll
    for (int i = 0; i < 4; i++) { e[i] = expf(z[i] - m); psum += e[i]; }
    red[tid] = psum; __syncthreads();
    for (int s = 128; s > 0; s >>= 1) { if (tid < s) red[tid] += red[tid + s]; __syncthreads(); }
    const float inv = 1.0f / red[0];
    #pragma unroll
    for (int i = 0; i < 4; i++)
        g_selh[r * N_ATOMS + tid + 256 * i] = __float2half(e[i] * inv);

    if (tid < N_FRAMES) {
        const float4* wp = (const float4*)(W_mom + tid * LATENT);
        float acc = 0.f;
        #pragma unroll
        for (int l4 = 0; l4 < LATENT / 4; l4++) {
            float4 w4 = wp[l4];
            acc += xs[l4 * 4 + 0] * w4.x + xs[l4 * 4 + 1] * w4.y
                 + xs[l4 * 4 + 2] * w4.z + xs[l4 * 4 + 3] * w4.w;
        }
        acc += b_mom[tid];
        const float sg = 1.0f / (1.0f + expf(-acc));
        lm[tid] = logf(1e-12f + 0.2f + 0.72f * sg);
    }
    __syncthreads();
    if (tid == 0) {
        float c = 0.f;
        for (int f = 0; f < N_FRAMES; f++) {
            c += lm[f];
            const float mm = expf(c);
            g_mom[r * N_FRAMES + f] = mm;
            if (write_mom) out_mom[r * N_FRAMES + f] = mm;
        }
    }
}

// ---------------------------------------------------------------------------
// K2: res = sel @ atoms, fp16 single-pass HMMA. B loaded [K][N] + ldmatrix.trans.
//     Fused: per-(row,block) hann^2-weighted norm partials -> g_p1/g_p2.
// ---------------------------------------------------------------------------
__global__ __launch_bounds__(256, 2) void k_gemm()
{
    extern __shared__ char sm_dyn[];
    __shared__ float hsq[WIN];
    __shared__ float s_part[4][BM][2];
    const uint32_t smem_u = smem_to_u32(sm_dyn);

    const int tid  = threadIdx.x;
    const int wid  = tid >> 5;
    const int lane = tid & 31;
    const int wm   = wid & 1;        // 2 warps in M  (64 rows)
    const int wn   = wid >> 1;       // 4 warps in N  (32 cols)
    const int mBase = blockIdx.x * BM;
    const int nBase = blockIdx.y * BN;

    hsq[tid] = g_hann[tid] * g_hann[tid];
    hsq[tid + 256] = g_hann[tid + 256] * g_hann[tid + 256];

    // ---- per-thread gmem->smem copy descriptors (4 x 16B per stage) ----
    // chunks: 0..511 A (128 rows x 4), 512..1023 B (32 rows x 16)
    const __half* srcp[4];
    uint32_t dstoff[4];
    size_t   kstep[4];
    #pragma unroll
    for (int i = 0; i < 4; i++) {
        const int q = tid + i * 256;
        if (q < 512) {
            const int row = q >> 2, c = q & 3;
            const int cs = c ^ ((row >> 1) & 3);
            srcp[i]   = g_selh + (size_t)(mBase + row) * N_ATOMS + c * 8;
            dstoff[i] = (uint32_t)(OFF_A + row * A_ROWB + cs * 16);
            kstep[i]  = BK;                       // advance along K (elements)
        } else {
            const int qb = q - 512;
            const int row = qb >> 4, c = qb & 15;
            const int cs = c ^ (row & 7);
            srcp[i]   = g_ath + (size_t)row * SAMPLES + nBase + c * 8;
            dstoff[i] = (uint32_t)(OFF_B + row * B_ROWB + cs * 16);
            kstep[i]  = (size_t)BK * SAMPLES;     // advance rows along K
        }
    }

    #define LOAD_STAGE(buf, tt) do {                                    \
        const uint32_t sb_ = smem_u + (uint32_t)(buf) * STAGE_B;        \
        _Pragma("unroll")                                               \
        for (int i_ = 0; i_ < 4; i_++)                                  \
            CP_ASYNC16(sb_ + dstoff[i_], srcp[i_] + (size_t)(tt) * kstep[i_]); \
        CP_COMMIT();                                                    \
    } while (0)

    // ---- A ldmatrix lane geometry (non-trans, 64B rows) ----
    const int a_lr = lane & 15;
    const int a_jb = lane >> 4;
    const int a_sw = (a_lr >> 1) & 3;
    const uint32_t a_rowoff = (uint32_t)(a_lr * A_ROWB);

    // ---- B ldmatrix.trans lane geometry (256B rows, chunk ^= row&7) ----
    // x4 tiles: t0=(k0:8,n0:8) t1=(k8:16,n0:8) t2=(k0:8,n8:16) t3=(k8:16,n8:16)
    const int b_tile  = lane >> 3;
    const int b_kloc  = (b_tile & 1) * 8 + (lane & 7);
    const int b_ngrp  = b_tile >> 1;
    const uint32_t b_base = (uint32_t)(OFF_B + b_kloc * B_ROWB);
    const int b_cs0 = (wn * 4 + 0 * 2 + b_ngrp) ^ (b_kloc & 7);   // x4 group g=0
    const int b_cs1 = (wn * 4 + 1 * 2 + b_ngrp) ^ (b_kloc & 7);   // g=1

    float c[4][4][4];
    #pragma unroll
    for (int mi = 0; mi < 4; mi++)
        #pragma unroll
        for (int ni = 0; ni < 4; ni++)
            #pragma unroll
            for (int k = 0; k < 4; k++) c[mi][ni][k] = 0.f;

    LOAD_STAGE(0, 0);
    LOAD_STAGE(1, 1);
    LOAD_STAGE(2, 2);
    LOAD_STAGE(3, 3);
    LOAD_STAGE(4, 4);

    for (int t = 0; t < NT; t++) {
        CP_WAIT4();                 // stage t complete (<=4 newer pending)
        __syncthreads();
        if (t + 5 < NT) LOAD_STAGE((t + 5) % NSTAGE, t + 5);

        const uint32_t buf = smem_u + (uint32_t)(t % NSTAGE) * STAGE_B;

        #pragma unroll
        for (int ks = 0; ks < 2; ks++) {          // two k16 steps in BK=32
            const uint32_t a_ch = (uint32_t)(((ks * 2 + a_jb) ^ a_sw) * 16);
            const uint32_t b_ko = (uint32_t)(ks * 16 * B_ROWB);

            uint32_t b0[4], b1[4];
            LDSM4T(b0, buf + b_base + b_ko + (uint32_t)(b_cs0 * 16));
            LDSM4T(b1, buf + b_base + b_ko + (uint32_t)(b_cs1 * 16));

            #pragma unroll
            for (int mi = 0; mi < 4; mi++) {
                uint32_t ah[4];
                const uint32_t a_addr = buf + (uint32_t)(OFF_A + (wm * 64 + mi * 16) * A_ROWB)
                                      + a_rowoff + a_ch;
                LDSM4(ah, a_addr);
                MMA_F16(c[mi][0], ah, b0[0], b0[1]);
                MMA_F16(c[mi][1], ah, b0[2], b0[3]);
                MMA_F16(c[mi][2], ah, b1[0], b1[1]);
                MMA_F16(c[mi][3], ah, b1[2], b1[3]);
            }
        }
    }

    // ---- epilogue 1: write C frags straight to g_res ----
    const int rbase = mBase + wm * 64 + (lane >> 2);
    const int cbase = nBase + wn * 32 + (lane & 3) * 2;
    #pragma unroll
    for (int mi = 0; mi < 4; mi++)
        #pragma unroll
        for (int ni = 0; ni < 4; ni++) {
            float* p = g_res + (size_t)(rbase + mi * 16) * SAMPLES + cbase + ni * 8;
            *(float2*)p                 = make_float2(c[mi][ni][0], c[mi][ni][1]);
            *(float2*)(p + 8 * SAMPLES) = make_float2(c[mi][ni][2], c[mi][ni][3]);
        }

    // ---- epilogue 2: hann^2-weighted norm partials for this 256-block ----
    // all tile columns live in block b = nBase>>8; j = (nBase&255) + local col
    const int jq = (nBase & 255) + wn * 32 + (lane & 3) * 2;
    #pragma unroll
    for (int mi = 0; mi < 4; mi++) {
        #pragma unroll
        for (int pr = 0; pr < 2; pr++) {
            float s1 = 0.f, s2 = 0.f;
            #pragma unroll
            for (int ni = 0; ni < 4; ni++) {
                #pragma unroll
                for (int e = 0; e < 2; e++) {
                    const float v = c[mi][ni][pr * 2 + e];
                    const int j = jq + ni * 8 + e;
                    s1 += v * v * hsq[j];
                    s2 += v * v * hsq[j + 256];
                }
            }
            s1 += __shfl_xor_sync(0xffffffffu, s1, 1);
            s1 += __shfl_xor_sync(0xffffffffu, s1, 2);
            s2 += __shfl_xor_sync(0xffffffffu, s2, 1);
            s2 += __shfl_xor_sync(0xffffffffu, s2, 2);
            if ((lane & 3) == 0) {
                const int rl = wm * 64 + mi * 16 + pr * 8 + (lane >> 2);
                s_part[wn][rl][0] = s1;
                s_part[wn][rl][1] = s2;
            }
        }
    }
    __syncthreads();
    if (tid < BM) {
        const float a1 = s_part[0][tid][0] + s_part[1][tid][0] + s_part[2][tid][0] + s_part[3][tid][0];
        const float a2 = s_part[0][tid][1] + s_part[1][tid][1] + s_part[2][tid][1] + s_part[3][tid][1];
        const int idx = (nBase >> 7);            // b*2 + half, 0..255
        g_p1[(size_t)(mBase + tid) * 256 + idx] = a1;
        g_p2[(size_t)(mBase + tid) * 256 + idx] = a2;
    }
    #undef LOAD_STAGE
}

// ---------------------------------------------------------------------------
// K3: scales from partials + pointwise scale + overlap-add. 1 block per row.
// ---------------------------------------------------------------------------
__global__ __launch_bounds__(256) void k_epilogue(float* __restrict__ out)
{
    __shared__ float hs[WIN];
    __shared__ float sc[N_FRAMES];
    const int r   = blockIdx.x;
    const int tid = threadIdx.x;
    hs[tid] = g_hann[tid]; hs[tid + 256] = g_hann[tid + 256];

    if (tid < N_FRAMES) {
        const float* p1 = g_p1 + (size_t)r * 256;
        const float* p2 = g_p2 + (size_t)r * 256;
        float n2 = p1[tid * 2] + p1[tid * 2 + 1];
        if (tid + 1 < N_FRAMES) n2 += p2[tid * 2 + 2] + p2[tid * 2 + 3];
        sc[tid] = g_mom[r * N_FRAMES + tid] / (sqrtf(n2) + 1e-8f);
    }
    __syncthreads();

    for (int s0 = tid * 4; s0 < SAMPLES; s0 += 1024) {
        const int f1 = s0 >> 8;
        const int j  = s0 & 255;
        const float g1 = sc[f1];
        const float g0 = (f1 > 0) ? sc[f1 - 1] : 0.f;
        float4 v = *(const float4*)(g_res + (size_t)r * SAMPLES + s0);
        float4 o;
        o.x = v.x * (hs[j + 0] * g1 + hs[j + 0 + HOP] * g0);
        o.y = v.y * (hs[j + 1] * g1 + hs[j + 1 + HOP] * g0);
        o.z = v.z * (hs[j + 2] * g1 + hs[j + 2 + HOP] * g0);
        o.w = v.w * (hs[j + 3] * g1 + hs[j + 3 + HOP] * g0);
        *(float4*)(out + (size_t)r * SAMPLES + s0) = o;
    }
}

// ---------------------------------------------------------------------------
extern "C" void kernel_launch(void* const* d_in, const int* in_sizes, int n_in,
                              void* d_out, int out_size)
{
    const float* x     = (const float*)d_in[0];
    const float* W_sel = (const float*)d_in[1];
    const float* b_sel = (const float*)d_in[2];
    const float* W_mom = (const float*)d_in[3];
    const float* b_mom = (const float*)d_in[4];
    const float* atoms = (const float*)d_in[5];

    float* out = (float*)d_out;
    const int audio_elems = R_ROWS * SAMPLES;
    const int write_mom = (out_size >= audio_elems + R_ROWS * N_FRAMES) ? 1 : 0;
    float* out_mom = out + audio_elems;

    cudaFuncSetAttribute(k_gemm, cudaFuncAttributeMaxDynamicSharedMemorySize, GEMM_SMEM);

    k_hann<<<1, WIN>>>();
    k_tofp16<<<4096, 256>>>(atoms);
    k_sel_mom<<<R_ROWS, 256>>>(x, W_sel, b_sel, W_mom, b_mom, out_mom, write_mom);
    // grid.x = M tiles (8) fastest -> CTAs sharing an atoms N-strip run together (L2 reuse)
    k_gemm<<<dim3(R_ROWS / BM, SAMPLES / BN), 256, GEMM_SMEM>>>();
    k_epilogue<<<R_ROWS, 256>>>(out);
}

// round 14
// speedup vs baseline: 4.7126x; 1.0385x over previous
#include <cuda_runtime.h>
#include <cuda_fp16.h>
#include <math.h>
#include <stdint.h>

// Problem dims
#define R_ROWS   1024      // B*E = 16*64
#define LATENT   128
#define N_ATOMS  1024      // K of the big GEMM
#define N_FRAMES 128
#define SAMPLES  32768
#define WIN      512
#define HOP      256

#define RES_SCALE 16.0f        // res stored as fp16*16 (keeps values normal);
#define RES_INV   (1.0f/16.0f) // folded into sc[] in the epilogue

// GEMM tiling: CTA 128x128, BK=32, 8 warps (warp tile 64x32), 2 CTAs/SM
// A smem: [M=128][K=32] fp16, 64B rows, XOR swizzle (chunk ^= (row>>1)&3)
// B smem: [K=32][N=128] fp16, 256B rows, XOR swizzle (chunk ^= row&7)
#define BM 128
#define BN 128
#define BK 32
#define NT (N_ATOMS / BK)      // 32 k-tiles
#define A_ROWB 64
#define B_ROWB 256
#define OFF_A  0
#define A_B    (128 * A_ROWB)            // 8192
#define OFF_B  (A_B)
#define B_B    (BK * B_ROWB)             // 8192
#define STAGE_B (A_B + B_B)              // 16384
#define NSTAGE 6
#define GEMM_SMEM (NSTAGE * STAGE_B)     // 98304 per CTA

// Scratch (static device globals — no runtime allocation allowed)
__device__ __half g_selh[R_ROWS * N_ATOMS];     // 2 MB (fp16 softmax weights)
__device__ __half g_ath [N_ATOMS * SAMPLES];    // atoms fp16, [K][N] native  64 MB
__device__ __half g_resh[R_ROWS * SAMPLES];     // 64 MB (16*res, fp16)
__device__ float g_p1[R_ROWS * 2 * N_FRAMES];   // per-(row,block,half) hann1^2 partials
__device__ float g_p2[R_ROWS * 2 * N_FRAMES];   // hann2^2 partials
__device__ float g_mom[R_ROWS * N_FRAMES];
__device__ float g_hann[WIN];

// ---------------------------------------------------------------------------
// low-level helpers (base-target sm_80+ instructions only)
// ---------------------------------------------------------------------------
__device__ __forceinline__ uint32_t smem_to_u32(const void* p) {
    uint32_t a;
    asm("{ .reg .u64 t; cvta.to.shared.u64 t, %1; cvt.u32.u64 %0, t; }" : "=r"(a) : "l"(p));
    return a;
}
#define CP_ASYNC16(dst, src) \
    asm volatile("cp.async.cg.shared.global [%0], [%1], 16;" :: "r"(dst), "l"(src))
#define CP_COMMIT()  asm volatile("cp.async.commit_group;" ::: "memory")
#define CP_WAIT4()   asm volatile("cp.async.wait_group 4;" ::: "memory")

#define LDSM4(r, addr) \
    asm volatile("ldmatrix.sync.aligned.m8n8.x4.shared.b16 {%0,%1,%2,%3}, [%4];" \
        : "=r"((r)[0]), "=r"((r)[1]), "=r"((r)[2]), "=r"((r)[3]) : "r"(addr))
#define LDSM4T(r, addr) \
    asm volatile("ldmatrix.sync.aligned.m8n8.x4.trans.shared.b16 {%0,%1,%2,%3}, [%4];" \
        : "=r"((r)[0]), "=r"((r)[1]), "=r"((r)[2]), "=r"((r)[3]) : "r"(addr))

#define MMA_F16(c, a, b0, b1) \
    asm volatile("mma.sync.aligned.m16n8k16.row.col.f32.f16.f16.f32 " \
        "{%0,%1,%2,%3},{%4,%5,%6,%7},{%8,%9},{%0,%1,%2,%3};" \
        : "+f"((c)[0]), "+f"((c)[1]), "+f"((c)[2]), "+f"((c)[3]) \
        : "r"((a)[0]), "r"((a)[1]), "r"((a)[2]), "r"((a)[3]), "r"(b0), "r"(b1))

// ---------------------------------------------------------------------------
// K0: hann window table (periodic)
// ---------------------------------------------------------------------------
__global__ void k_hann() {
    int w = threadIdx.x;
    if (w < WIN)
        g_hann[w] = 0.5f * (1.0f - cosf((float)(2.0 * 3.14159265358979323846 / (double)WIN) * (float)w));
}

// ---------------------------------------------------------------------------
// K_C: atoms f32 [K][S] -> fp16 [K][S] (pure streaming convert, no transpose)
// ---------------------------------------------------------------------------
__global__ __launch_bounds__(256) void k_tofp16(const float* __restrict__ atoms)
{
    const size_t total4 = (size_t)N_ATOMS * SAMPLES / 4;
    for (size_t i = (size_t)blockIdx.x * 256 + threadIdx.x; i < total4;
         i += (size_t)gridDim.x * 256) {
        float4 v = ((const float4*)atoms)[i];
        __half2 h0 = __floats2half2_rn(v.x, v.y);
        __half2 h1 = __floats2half2_rn(v.z, v.w);
        ((uint2*)g_ath)[i] = make_uint2(*(uint32_t*)&h0, *(uint32_t*)&h1);
    }
}

// ---------------------------------------------------------------------------
// K1: per-row selection softmax (-> fp16) + momentum cumprod
// ---------------------------------------------------------------------------
__global__ __launch_bounds__(256) void k_sel_mom(
    const float* __restrict__ x,
    const float* __restrict__ W_sel, const float* __restrict__ b_sel,
    const float* __restrict__ W_mom, const float* __restrict__ b_mom,
    float* __restrict__ out_mom, int write_mom)
{
    __shared__ float xs[LATENT];
    __shared__ float red[256];
    __shared__ float lm[N_FRAMES];

    const int r   = blockIdx.x;
    const int tid = threadIdx.x;

    if (tid < LATENT) xs[tid] = x[r * LATENT + tid];
    __syncthreads();

    float z[4];
    #pragma unroll
    for (int i = 0; i < 4; i++) {
        const int a = tid + 256 * i;
        const float4* wp = (const float4*)(W_sel + a * LATENT);
        float acc = 0.f;
        #pragma unroll
        for (int l4 = 0; l4 < LATENT / 4; l4++) {
            float4 w4 = wp[l4];
            acc += xs[l4 * 4 + 0] * w4.x + xs[l4 * 4 + 1] * w4.y
                 + xs[l4 * 4 + 2] * w4.z + xs[l4 * 4 + 3] * w4.w;
        }
        z[i] = acc + b_sel[a];
    }

    float m = fmaxf(fmaxf(z[0], z[1]), fmaxf(z[2], z[3]));
    red[tid] = m; __syncthreads();
    for (int s = 128; s > 0; s >>= 1) { if (tid < s) red[tid] = fmaxf(red[tid], red[tid + s]); __syncthreads(); }
    m = red[0]; __syncthreads();

    float e[4], psum = 0.f;
    #pragma unroll
    for (int i = 0; i < 4; i++) { e[i] = expf(z[i] - m); psum += e[i]; }
    red[tid] = psum; __syncthreads();
    for (int s = 128; s > 0; s >>= 1) { if (tid < s) red[tid] += red[tid + s]; __syncthreads(); }
    const float inv = 1.0f / red[0];
    #pragma unroll
    for (int i = 0; i < 4; i++)
        g_selh[r * N_ATOMS + tid + 256 * i] = __float2half(e[i] * inv);

    if (tid < N_FRAMES) {
        const float4* wp = (const float4*)(W_mom + tid * LATENT);
        float acc = 0.f;
        #pragma unroll
        for (int l4 = 0; l4 < LATENT / 4; l4++) {
            float4 w4 = wp[l4];
            acc += xs[l4 * 4 + 0] * w4.x + xs[l4 * 4 + 1] * w4.y
                 + xs[l4 * 4 + 2] * w4.z + xs[l4 * 4 + 3] * w4.w;
        }
        acc += b_mom[tid];
        const float sg = 1.0f / (1.0f + expf(-acc));
        lm[tid] = logf(1e-12f + 0.2f + 0.72f * sg);
    }
    __syncthreads();
    if (tid == 0) {
        float c = 0.f;
        for (int f = 0; f < N_FRAMES; f++) {
            c += lm[f];
            const float mm = expf(c);
            g_mom[r * N_FRAMES + f] = mm;
            if (write_mom) out_mom[r * N_FRAMES + f] = mm;
        }
    }
}

// ---------------------------------------------------------------------------
// K2: res = sel @ atoms, fp16 single-pass HMMA. B loaded [K][N] + ldmatrix.trans.
//     Fused: per-(row,block) hann^2-weighted norm partials (exact f32) -> g_p1/g_p2.
//     res stored fp16 scaled by 16.
// ---------------------------------------------------------------------------
__global__ __launch_bounds__(256, 2) void k_gemm()
{
    extern __shared__ char sm_dyn[];
    __shared__ float hsq[WIN];
    __shared__ float s_part[4][BM][2];
    const uint32_t smem_u = smem_to_u32(sm_dyn);

    const int tid  = threadIdx.x;
    const int wid  = tid >> 5;
    const int lane = tid & 31;
    const int wm   = wid & 1;        // 2 warps in M  (64 rows)
    const int wn   = wid >> 1;       // 4 warps in N  (32 cols)
    const int mBase = blockIdx.x * BM;
    const int nBase = blockIdx.y * BN;

    hsq[tid] = g_hann[tid] * g_hann[tid];
    hsq[tid + 256] = g_hann[tid + 256] * g_hann[tid + 256];

    // ---- per-thread gmem->smem copy descriptors (4 x 16B per stage) ----
    // chunks: 0..511 A (128 rows x 4), 512..1023 B (32 rows x 16)
    const __half* srcp[4];
    uint32_t dstoff[4];
    size_t   kstep[4];
    #pragma unroll
    for (int i = 0; i < 4; i++) {
        const int q = tid + i * 256;
        if (q < 512) {
            const int row = q >> 2, c = q & 3;
            const int cs = c ^ ((row >> 1) & 3);
            srcp[i]   = g_selh + (size_t)(mBase + row) * N_ATOMS + c * 8;
            dstoff[i] = (uint32_t)(OFF_A + row * A_ROWB + cs * 16);
            kstep[i]  = BK;                       // advance along K (elements)
        } else {
            const int qb = q - 512;
            const int row = qb >> 4, c = qb & 15;
            const int cs = c ^ (row & 7);
            srcp[i]   = g_ath + (size_t)row * SAMPLES + nBase + c * 8;
            dstoff[i] = (uint32_t)(OFF_B + row * B_ROWB + cs * 16);
            kstep[i]  = (size_t)BK * SAMPLES;     // advance rows along K
        }
    }

    #define LOAD_STAGE(buf, tt) do {                                    \
        const uint32_t sb_ = smem_u + (uint32_t)(buf) * STAGE_B;        \
        _Pragma("unroll")                                               \
        for (int i_ = 0; i_ < 4; i_++)                                  \
            CP_ASYNC16(sb_ + dstoff[i_], srcp[i_] + (size_t)(tt) * kstep[i_]); \
        CP_COMMIT();                                                    \
    } while (0)

    // ---- A ldmatrix lane geometry (non-trans, 64B rows) ----
    const int a_lr = lane & 15;
    const int a_jb = lane >> 4;
    const int a_sw = (a_lr >> 1) & 3;
    const uint32_t a_rowoff = (uint32_t)(a_lr * A_ROWB);

    // ---- B ldmatrix.trans lane geometry (256B rows, chunk ^= row&7) ----
    const int b_tile  = lane >> 3;
    const int b_kloc  = (b_tile & 1) * 8 + (lane & 7);
    const int b_ngrp  = b_tile >> 1;
    const uint32_t b_base = (uint32_t)(OFF_B + b_kloc * B_ROWB);
    const int b_cs0 = (wn * 4 + 0 * 2 + b_ngrp) ^ (b_kloc & 7);   // x4 group g=0
    const int b_cs1 = (wn * 4 + 1 * 2 + b_ngrp) ^ (b_kloc & 7);   // g=1

    float c[4][4][4];
    #pragma unroll
    for (int mi = 0; mi < 4; mi++)
        #pragma unroll
        for (int ni = 0; ni < 4; ni++)
            #pragma unroll
            for (int k = 0; k < 4; k++) c[mi][ni][k] = 0.f;

    LOAD_STAGE(0, 0);
    LOAD_STAGE(1, 1);
    LOAD_STAGE(2, 2);
    LOAD_STAGE(3, 3);
    LOAD_STAGE(4, 4);

    for (int t = 0; t < NT; t++) {
        CP_WAIT4();                 // stage t complete (<=4 newer pending)
        __syncthreads();
        if (t + 5 < NT) LOAD_STAGE((t + 5) % NSTAGE, t + 5);

        const uint32_t buf = smem_u + (uint32_t)(t % NSTAGE) * STAGE_B;

        #pragma unroll
        for (int ks = 0; ks < 2; ks++) {          // two k16 steps in BK=32
            const uint32_t a_ch = (uint32_t)(((ks * 2 + a_jb) ^ a_sw) * 16);
            const uint32_t b_ko = (uint32_t)(ks * 16 * B_ROWB);

            uint32_t b0[4], b1[4];
            LDSM4T(b0, buf + b_base + b_ko + (uint32_t)(b_cs0 * 16));
            LDSM4T(b1, buf + b_base + b_ko + (uint32_t)(b_cs1 * 16));

            #pragma unroll
            for (int mi = 0; mi < 4; mi++) {
                uint32_t ah[4];
                const uint32_t a_addr = buf + (uint32_t)(OFF_A + (wm * 64 + mi * 16) * A_ROWB)
                                      + a_rowoff + a_ch;
                LDSM4(ah, a_addr);
                MMA_F16(c[mi][0], ah, b0[0], b0[1]);
                MMA_F16(c[mi][1], ah, b0[2], b0[3]);
                MMA_F16(c[mi][2], ah, b1[0], b1[1]);
                MMA_F16(c[mi][3], ah, b1[2], b1[3]);
            }
        }
    }

    // ---- epilogue 1: write 16*res as fp16 ----
    const int rbase = mBase + wm * 64 + (lane >> 2);
    const int cbase = nBase + wn * 32 + (lane & 3) * 2;
    #pragma unroll
    for (int mi = 0; mi < 4; mi++)
        #pragma unroll
        for (int ni = 0; ni < 4; ni++) {
            __half* p = g_resh + (size_t)(rbase + mi * 16) * SAMPLES + cbase + ni * 8;
            __half2 h0 = __floats2half2_rn(c[mi][ni][0] * RES_SCALE, c[mi][ni][1] * RES_SCALE);
            __half2 h1 = __floats2half2_rn(c[mi][ni][2] * RES_SCALE, c[mi][ni][3] * RES_SCALE);
            *(uint32_t*)p                 = *(uint32_t*)&h0;
            *(uint32_t*)(p + 8 * SAMPLES) = *(uint32_t*)&h1;
        }

    // ---- epilogue 2: hann^2-weighted norm partials for this 256-block (exact f32) ----
    const int jq = (nBase & 255) + wn * 32 + (lane & 3) * 2;
    #pragma unroll
    for (int mi = 0; mi < 4; mi++) {
        #pragma unroll
        for (int pr = 0; pr < 2; pr++) {
            float s1 = 0.f, s2 = 0.f;
            #pragma unroll
            for (int ni = 0; ni < 4; ni++) {
                #pragma unroll
                for (int e = 0; e < 2; e++) {
                    const float v = c[mi][ni][pr * 2 + e];
                    const int j = jq + ni * 8 + e;
                    s1 += v * v * hsq[j];
                    s2 += v * v * hsq[j + 256];
                }
            }
            s1 += __shfl_xor_sync(0xffffffffu, s1, 1);
            s1 += __shfl_xor_sync(0xffffffffu, s1, 2);
            s2 += __shfl_xor_sync(0xffffffffu, s2, 1);
            s2 += __shfl_xor_sync(0xffffffffu, s2, 2);
            if ((lane & 3) == 0) {
                const int rl = wm * 64 + mi * 16 + pr * 8 + (lane >> 2);
                s_part[wn][rl][0] = s1;
                s_part[wn][rl][1] = s2;
            }
        }
    }
    __syncthreads();
    if (tid < BM) {
        const float a1 = s_part[0][tid][0] + s_part[1][tid][0] + s_part[2][tid][0] + s_part[3][tid][0];
        const float a2 = s_part[0][tid][1] + s_part[1][tid][1] + s_part[2][tid][1] + s_part[3][tid][1];
        const int idx = (nBase >> 7);            // b*2 + half, 0..255
        g_p1[(size_t)(mBase + tid) * 256 + idx] = a1;
        g_p2[(size_t)(mBase + tid) * 256 + idx] = a2;
    }
    #undef LOAD_STAGE
}

// ---------------------------------------------------------------------------
// K3: scales from partials + pointwise scale + overlap-add. 1 block per row.
//     sc folds the 1/16 res scale.
// ---------------------------------------------------------------------------
__global__ __launch_bounds__(256) void k_epilogue(float* __restrict__ out)
{
    __shared__ float hs[WIN];
    __shared__ float sc[N_FRAMES];
    const int r   = blockIdx.x;
    const int tid = threadIdx.x;
    hs[tid] = g_hann[tid]; hs[tid + 256] = g_hann[tid + 256];

    if (tid < N_FRAMES) {
        const float* p1 = g_p1 + (size_t)r * 256;
        const float* p2 = g_p2 + (size_t)r * 256;
        float n2 = p1[tid * 2] + p1[tid * 2 + 1];
        if (tid + 1 < N_FRAMES) n2 += p2[tid * 2 + 2] + p2[tid * 2 + 3];
        sc[tid] = g_mom[r * N_FRAMES + tid] / (sqrtf(n2) + 1e-8f) * RES_INV;
    }
    __syncthreads();

    for (int s0 = tid * 4; s0 < SAMPLES; s0 += 1024) {
        const int f1 = s0 >> 8;
        const int j  = s0 & 255;
        const float g1 = sc[f1];
        const float g0 = (f1 > 0) ? sc[f1 - 1] : 0.f;
        uint2 rv = *(const uint2*)(g_resh + (size_t)r * SAMPLES + s0);
        float2 v0 = __half22float2(*(__half2*)&rv.x);
        float2 v1 = __half22float2(*(__half2*)&rv.y);
        float4 o;
        o.x = v0.x * (hs[j + 0] * g1 + hs[j + 0 + HOP] * g0);
        o.y = v0.y * (hs[j + 1] * g1 + hs[j + 1 + HOP] * g0);
        o.z = v1.x * (hs[j + 2] * g1 + hs[j + 2 + HOP] * g0);
        o.w = v1.y * (hs[j + 3] * g1 + hs[j + 3 + HOP] * g0);
        *(float4*)(out + (size_t)r * SAMPLES + s0) = o;
    }
}

// ---------------------------------------------------------------------------
extern "C" void kernel_launch(void* const* d_in, const int* in_sizes, int n_in,
                              void* d_out, int out_size)
{
    const float* x     = (const float*)d_in[0];
    const float* W_sel = (const float*)d_in[1];
    const float* b_sel = (const float*)d_in[2];
    const float* W_mom = (const float*)d_in[3];
    const float* b_mom = (const float*)d_in[4];
    const float* atoms = (const float*)d_in[5];

    float* out = (float*)d_out;
    const int audio_elems = R_ROWS * SAMPLES;
    const int write_mom = (out_size >= audio_elems + R_ROWS * N_FRAMES) ? 1 : 0;
    float* out_mom = out + audio_elems;

    cudaFuncSetAttribute(k_gemm, cudaFuncAttributeMaxDynamicSharedMemorySize, GEMM_SMEM);

    k_hann<<<1, WIN>>>();
    k_tofp16<<<4096, 256>>>(atoms);
    k_sel_mom<<<R_ROWS, 256>>>(x, W_sel, b_sel, W_mom, b_mom, out_mom, write_mom);
    // grid.x = M tiles (8) fastest -> CTAs sharing an atoms N-strip run together (L2 reuse)
    k_gemm<<<dim3(R_ROWS / BM, SAMPLES / BN), 256, GEMM_SMEM>>>();
    k_epilogue<<<R_ROWS, 256>>>(out);
}

// round 15
// speedup vs baseline: 4.8536x; 1.0299x over previous
#include <cuda_runtime.h>
#include <cuda_fp16.h>
#include <math.h>
#include <stdint.h>

// Problem dims
#define R_ROWS   1024      // B*E = 16*64
#define LATENT   128
#define N_ATOMS  1024      // K of the big GEMM
#define N_FRAMES 128
#define SAMPLES  32768
#define WIN      512
#define HOP      256

#define RES_SCALE 16.0f        // res stored as fp16*16 (keeps values normal);
#define RES_INV   (1.0f/16.0f) // folded into sc[] in the epilogue

// GEMM tiling: CTA 128x128, BK=64, 8 warps (warp tile 64x32), 2 CTAs/SM
// A smem: [M=128][K=64] fp16, 128B rows, XOR swizzle (chunk ^= row&7)
// B smem: [K=64][N=128] fp16, 256B rows, XOR swizzle (chunk ^= row&7)
#define BM 128
#define BN 128
#define BK 64
#define NT (N_ATOMS / BK)      // 16 k-tiles
#define A_ROWB 128
#define B_ROWB 256
#define OFF_A  0
#define A_B    (128 * A_ROWB)            // 16384
#define OFF_B  (A_B)
#define B_B    (BK * B_ROWB)             // 16384
#define STAGE_B (A_B + B_B)              // 32768
#define NSTAGE 3
#define GEMM_SMEM (NSTAGE * STAGE_B)     // 98304 per CTA

// Scratch (static device globals — no runtime allocation allowed)
__device__ __half g_selh[R_ROWS * N_ATOMS];     // 2 MB (fp16 softmax weights)
__device__ __half g_ath [N_ATOMS * SAMPLES];    // atoms fp16, [K][N] native  64 MB
__device__ __half g_resh[R_ROWS * SAMPLES];     // 64 MB (16*res, fp16)
__device__ float g_p1[R_ROWS * 2 * N_FRAMES];   // per-(row,block,half) hann1^2 partials
__device__ float g_p2[R_ROWS * 2 * N_FRAMES];   // hann2^2 partials
__device__ float g_mom[R_ROWS * N_FRAMES];
__device__ float g_hann[WIN];

// ---------------------------------------------------------------------------
// low-level helpers (base-target sm_80+ instructions only)
// ---------------------------------------------------------------------------
__device__ __forceinline__ uint32_t smem_to_u32(const void* p) {
    uint32_t a;
    asm("{ .reg .u64 t; cvta.to.shared.u64 t, %1; cvt.u32.u64 %0, t; }" : "=r"(a) : "l"(p));
    return a;
}
#define CP_ASYNC16(dst, src) \
    asm volatile("cp.async.cg.shared.global [%0], [%1], 16;" :: "r"(dst), "l"(src))
#define CP_COMMIT()  asm volatile("cp.async.commit_group;" ::: "memory")
#define CP_WAIT1()   asm volatile("cp.async.wait_group 1;" ::: "memory")
#define CP_WAIT0()   asm volatile("cp.async.wait_group 0;" ::: "memory")

#define LDSM4(r, addr) \
    asm volatile("ldmatrix.sync.aligned.m8n8.x4.shared.b16 {%0,%1,%2,%3}, [%4];" \
        : "=r"((r)[0]), "=r"((r)[1]), "=r"((r)[2]), "=r"((r)[3]) : "r"(addr))
#define LDSM4T(r, addr) \
    asm volatile("ldmatrix.sync.aligned.m8n8.x4.trans.shared.b16 {%0,%1,%2,%3}, [%4];" \
        : "=r"((r)[0]), "=r"((r)[1]), "=r"((r)[2]), "=r"((r)[3]) : "r"(addr))

#define MMA_F16(c, a, b0, b1) \
    asm volatile("mma.sync.aligned.m16n8k16.row.col.f32.f16.f16.f32 " \
        "{%0,%1,%2,%3},{%4,%5,%6,%7},{%8,%9},{%0,%1,%2,%3};" \
        : "+f"((c)[0]), "+f"((c)[1]), "+f"((c)[2]), "+f"((c)[3]) \
        : "r"((a)[0]), "r"((a)[1]), "r"((a)[2]), "r"((a)[3]), "r"(b0), "r"(b1))

// ---------------------------------------------------------------------------
// K0: hann window table (periodic)
// ---------------------------------------------------------------------------
__global__ void k_hann() {
    int w = threadIdx.x;
    if (w < WIN)
        g_hann[w] = 0.5f * (1.0f - cosf((float)(2.0 * 3.14159265358979323846 / (double)WIN) * (float)w));
}

// ---------------------------------------------------------------------------
// K_C: atoms f32 [K][S] -> fp16 [K][S] (pure streaming convert, no transpose)
// ---------------------------------------------------------------------------
__global__ __launch_bounds__(256) void k_tofp16(const float* __restrict__ atoms)
{
    const size_t total4 = (size_t)N_ATOMS * SAMPLES / 4;
    for (size_t i = (size_t)blockIdx.x * 256 + threadIdx.x; i < total4;
         i += (size_t)gridDim.x * 256) {
        float4 v = ((const float4*)atoms)[i];
        __half2 h0 = __floats2half2_rn(v.x, v.y);
        __half2 h1 = __floats2half2_rn(v.z, v.w);
        ((uint2*)g_ath)[i] = make_uint2(*(uint32_t*)&h0, *(uint32_t*)&h1);
    }
}

// ---------------------------------------------------------------------------
// K1: per-row selection softmax (-> fp16) + momentum cumprod
// ---------------------------------------------------------------------------
__global__ __launch_bounds__(256) void k_sel_mom(
    const float* __restrict__ x,
    const float* __restrict__ W_sel, const float* __restrict__ b_sel,
    const float* __restrict__ W_mom, const float* __restrict__ b_mom,
    float* __restrict__ out_mom, int write_mom)
{
    __shared__ float xs[LATENT];
    __shared__ float red[256];
    __shared__ float lm[N_FRAMES];

    const int r   = blockIdx.x;
    const int tid = threadIdx.x;

    if (tid < LATENT) xs[tid] = x[r * LATENT + tid];
    __syncthreads();

    float z[4];
    #pragma unroll
    for (int i = 0; i < 4; i++) {
        const int a = tid + 256 * i;
        const float4* wp = (const float4*)(W_sel + a * LATENT);
        float acc = 0.f;
        #pragma unroll
        for (int l4 = 0; l4 < LATENT / 4; l4++) {
            float4 w4 = wp[l4];
            acc += xs[l4 * 4 + 0] * w4.x + xs[l4 * 4 + 1] * w4.y
                 + xs[l4 * 4 + 2] * w4.z + xs[l4 * 4 + 3] * w4.w;
        }
        z[i] = acc + b_sel[a];
    }

    float m = fmaxf(fmaxf(z[0], z[1]), fmaxf(z[2], z[3]));
    red[tid] = m; __syncthreads();
    for (int s = 128; s > 0; s >>= 1) { if (tid < s) red[tid] = fmaxf(red[tid], red[tid + s]); __syncthreads(); }
    m = red[0]; __syncthreads();

    float e[4], psum = 0.f;
    #pragma unroll
    for (int i = 0; i < 4; i++) { e[i] = expf(z[i] - m); psum += e[i]; }
    red[tid] = psum; __syncthreads();
    for (int s = 128; s > 0; s >>= 1) { if (tid < s) red[tid] += red[tid + s]; __syncthreads(); }
    const float inv = 1.0f / red[0];
    #pragma unroll
    for (int i = 0; i < 4; i++)
        g_selh[r * N_ATOMS + tid + 256 * i] = __float2half(e[i] * inv);

    if (tid < N_FRAMES) {
        const float4* wp = (const float4*)(W_mom + tid * LATENT);
        float acc = 0.f;
        #pragma unroll
        for (int l4 = 0; l4 < LATENT / 4; l4++) {
            float4 w4 = wp[l4];
            acc += xs[l4 * 4 + 0] * w4.x + xs[l4 * 4 + 1] * w4.y
                 + xs[l4 * 4 + 2] * w4.z + xs[l4 * 4 + 3] * w4.w;
        }
        acc += b_mom[tid];
        const float sg = 1.0f / (1.0f + expf(-acc));
        lm[tid] = logf(1e-12f + 0.2f + 0.72f * sg);
    }
    __syncthreads();
    if (tid == 0) {
        float c = 0.f;
        for (int f = 0; f < N_FRAMES; f++) {
            c += lm[f];
            const float mm = expf(c);
            g_mom[r * N_FRAMES + f] = mm;
            if (write_mom) out_mom[r * N_FRAMES + f] = mm;
        }
    }
}

// ---------------------------------------------------------------------------
// K2: res = sel @ atoms, fp16 single-pass HMMA. BK=64, 1 barrier per 64-K.
//     Fused: per-(row,block) hann^2-weighted norm partials (exact f32).
//     res stored fp16 scaled by 16.
// ---------------------------------------------------------------------------
__global__ __launch_bounds__(256, 2) void k_gemm()
{
    extern __shared__ char sm_dyn[];
    __shared__ float hsq[WIN];
    __shared__ float s_part[4][BM][2];
    const uint32_t smem_u = smem_to_u32(sm_dyn);

    const int tid  = threadIdx.x;
    const int wid  = tid >> 5;
    const int lane = tid & 31;
    const int wm   = wid & 1;        // 2 warps in M  (64 rows)
    const int wn   = wid >> 1;       // 4 warps in N  (32 cols)
    const int mBase = blockIdx.x * BM;
    const int nBase = blockIdx.y * BN;

    hsq[tid] = g_hann[tid] * g_hann[tid];
    hsq[tid + 256] = g_hann[tid + 256] * g_hann[tid + 256];

    // ---- per-thread gmem->smem copy descriptors (8 x 16B per stage) ----
    // chunks: 0..1023 A (128 rows x 8), 1024..2047 B (64 rows x 16)
    const __half* srcp[8];
    uint32_t dstoff[8];
    size_t   kstep[8];
    #pragma unroll
    for (int i = 0; i < 8; i++) {
        const int q = tid + i * 256;
        if (q < 1024) {
            const int row = q >> 3, c = q & 7;
            const int cs = c ^ (row & 7);
            srcp[i]   = g_selh + (size_t)(mBase + row) * N_ATOMS + c * 8;
            dstoff[i] = (uint32_t)(OFF_A + row * A_ROWB + cs * 16);
            kstep[i]  = BK;                       // advance along K (elements)
        } else {
            const int qb = q - 1024;
            const int row = qb >> 4, c = qb & 15;
            const int cs = c ^ (row & 7);
            srcp[i]   = g_ath + (size_t)row * SAMPLES + nBase + c * 8;
            dstoff[i] = (uint32_t)(OFF_B + row * B_ROWB + cs * 16);
            kstep[i]  = (size_t)BK * SAMPLES;     // advance rows along K
        }
    }

    // pointer-advancing stage load (loads issued monotonically)
    #define LOAD_STAGE(buf) do {                                        \
        const uint32_t sb_ = smem_u + (uint32_t)(buf) * STAGE_B;        \
        _Pragma("unroll")                                               \
        for (int i_ = 0; i_ < 8; i_++) {                                \
            CP_ASYNC16(sb_ + dstoff[i_], srcp[i_]);                     \
            srcp[i_] += kstep[i_];                                      \
        }                                                               \
        CP_COMMIT();                                                    \
    } while (0)

    // ---- A ldmatrix lane geometry (non-trans, 128B rows, chunk ^= row&7) ----
    const int a_lr = lane & 15;
    const int a_jb = lane >> 4;
    const int a_sw = a_lr & 7;
    const uint32_t a_rowoff = (uint32_t)(a_lr * A_ROWB);

    // ---- B ldmatrix.trans lane geometry (256B rows, chunk ^= row&7) ----
    const int b_tile  = lane >> 3;
    const int b_kloc  = (b_tile & 1) * 8 + (lane & 7);
    const int b_ngrp  = b_tile >> 1;
    const uint32_t b_base = (uint32_t)(OFF_B + b_kloc * B_ROWB);
    const int b_cs0 = (wn * 4 + 0 * 2 + b_ngrp) ^ (b_kloc & 7);   // x4 group g=0
    const int b_cs1 = (wn * 4 + 1 * 2 + b_ngrp) ^ (b_kloc & 7);   // g=1

    float c[4][4][4];
    #pragma unroll
    for (int mi = 0; mi < 4; mi++)
        #pragma unroll
        for (int ni = 0; ni < 4; ni++)
            #pragma unroll
            for (int k = 0; k < 4; k++) c[mi][ni][k] = 0.f;

    LOAD_STAGE(0);
    LOAD_STAGE(1);

    for (int t = 0; t < NT; t++) {
        if (t == NT - 1) { CP_WAIT0(); } else { CP_WAIT1(); }
        __syncthreads();
        if (t + 2 < NT) LOAD_STAGE((t + 2) % NSTAGE);

        const uint32_t buf = smem_u + (uint32_t)(t % NSTAGE) * STAGE_B;

        #pragma unroll
        for (int ks = 0; ks < 4; ks++) {          // four k16 steps in BK=64
            const uint32_t a_ch = (uint32_t)(((ks * 2 + a_jb) ^ a_sw) * 16);
            const uint32_t b_ko = (uint32_t)(ks * 16 * B_ROWB);

            uint32_t b0[4], b1[4];
            LDSM4T(b0, buf + b_base + b_ko + (uint32_t)(b_cs0 * 16));
            LDSM4T(b1, buf + b_base + b_ko + (uint32_t)(b_cs1 * 16));

            #pragma unroll
            for (int mi = 0; mi < 4; mi++) {
                uint32_t ah[4];
                const uint32_t a_addr = buf + (uint32_t)(OFF_A + (wm * 64 + mi * 16) * A_ROWB)
                                      + a_rowoff + a_ch;
                LDSM4(ah, a_addr);
                MMA_F16(c[mi][0], ah, b0[0], b0[1]);
                MMA_F16(c[mi][1], ah, b0[2], b0[3]);
                MMA_F16(c[mi][2], ah, b1[0], b1[1]);
                MMA_F16(c[mi][3], ah, b1[2], b1[3]);
            }
        }
    }

    // ---- epilogue 1: write 16*res as fp16 ----
    const int rbase = mBase + wm * 64 + (lane >> 2);
    const int cbase = nBase + wn * 32 + (lane & 3) * 2;
    #pragma unroll
    for (int mi = 0; mi < 4; mi++)
        #pragma unroll
        for (int ni = 0; ni < 4; ni++) {
            __half* p = g_resh + (size_t)(rbase + mi * 16) * SAMPLES + cbase + ni * 8;
            __half2 h0 = __floats2half2_rn(c[mi][ni][0] * RES_SCALE, c[mi][ni][1] * RES_SCALE);
            __half2 h1 = __floats2half2_rn(c[mi][ni][2] * RES_SCALE, c[mi][ni][3] * RES_SCALE);
            *(uint32_t*)p                 = *(uint32_t*)&h0;
            *(uint32_t*)(p + 8 * SAMPLES) = *(uint32_t*)&h1;
        }

    // ---- epilogue 2: hann^2-weighted norm partials for this 256-block (exact f32) ----
    const int jq = (nBase & 255) + wn * 32 + (lane & 3) * 2;
    #pragma unroll
    for (int mi = 0; mi < 4; mi++) {
        #pragma unroll
        for (int pr = 0; pr < 2; pr++) {
            float s1 = 0.f, s2 = 0.f;
            #pragma unroll
            for (int ni = 0; ni < 4; ni++) {
                #pragma unroll
                for (int e = 0; e < 2; e++) {
                    const float v = c[mi][ni][pr * 2 + e];
                    const int j = jq + ni * 8 + e;
                    s1 += v * v * hsq[j];
                    s2 += v * v * hsq[j + 256];
                }
            }
            s1 += __shfl_xor_sync(0xffffffffu, s1, 1);
            s1 += __shfl_xor_sync(0xffffffffu, s1, 2);
            s2 += __shfl_xor_sync(0xffffffffu, s2, 1);
            s2 += __shfl_xor_sync(0xffffffffu, s2, 2);
            if ((lane & 3) == 0) {
                const int rl = wm * 64 + mi * 16 + pr * 8 + (lane >> 2);
                s_part[wn][rl][0] = s1;
                s_part[wn][rl][1] = s2;
            }
        }
    }
    __syncthreads();
    if (tid < BM) {
        const float a1 = s_part[0][tid][0] + s_part[1][tid][0] + s_part[2][tid][0] + s_part[3][tid][0];
        const float a2 = s_part[0][tid][1] + s_part[1][tid][1] + s_part[2][tid][1] + s_part[3][tid][1];
        const int idx = (nBase >> 7);            // b*2 + half, 0..255
        g_p1[(size_t)(mBase + tid) * 256 + idx] = a1;
        g_p2[(size_t)(mBase + tid) * 256 + idx] = a2;
    }
    #undef LOAD_STAGE
}

// ---------------------------------------------------------------------------
// K3: scales from partials + pointwise scale + overlap-add.
//     grid (2, R_ROWS): 2 blocks per row, each streams half the samples.
// ---------------------------------------------------------------------------
__global__ __launch_bounds__(256) void k_epilogue(float* __restrict__ out)
{
    __shared__ float hs[WIN];
    __shared__ float sc[N_FRAMES];
    const int r    = blockIdx.y;
    const int half = blockIdx.x;
    const int tid  = threadIdx.x;
    hs[tid] = g_hann[tid]; hs[tid + 256] = g_hann[tid + 256];

    if (tid < N_FRAMES) {
        const float* p1 = g_p1 + (size_t)r * 256;
        const float* p2 = g_p2 + (size_t)r * 256;
        float n2 = p1[tid * 2] + p1[tid * 2 + 1];
        if (tid + 1 < N_FRAMES) n2 += p2[tid * 2 + 2] + p2[tid * 2 + 3];
        sc[tid] = g_mom[r * N_FRAMES + tid] / (sqrtf(n2) + 1e-8f) * RES_INV;
    }
    __syncthreads();

    const int sBeg = half * (SAMPLES / 2);
    for (int s0 = sBeg + tid * 4; s0 < sBeg + SAMPLES / 2; s0 += 1024) {
        const int f1 = s0 >> 8;
        const int j  = s0 & 255;
        const float g1 = sc[f1];
        const float g0 = (f1 > 0) ? sc[f1 - 1] : 0.f;
        uint2 rv = *(const uint2*)(g_resh + (size_t)r * SAMPLES + s0);
        float2 v0 = __half22float2(*(__half2*)&rv.x);
        float2 v1 = __half22float2(*(__half2*)&rv.y);
        float4 o;
        o.x = v0.x * (hs[j + 0] * g1 + hs[j + 0 + HOP] * g0);
        o.y = v0.y * (hs[j + 1] * g1 + hs[j + 1 + HOP] * g0);
        o.z = v1.x * (hs[j + 2] * g1 + hs[j + 2 + HOP] * g0);
        o.w = v1.y * (hs[j + 3] * g1 + hs[j + 3 + HOP] * g0);
        *(float4*)(out + (size_t)r * SAMPLES + s0) = o;
    }
}

// ---------------------------------------------------------------------------
extern "C" void kernel_launch(void* const* d_in, const int* in_sizes, int n_in,
                              void* d_out, int out_size)
{
    const float* x     = (const float*)d_in[0];
    const float* W_sel = (const float*)d_in[1];
    const float* b_sel = (const float*)d_in[2];
    const float* W_mom = (const float*)d_in[3];
    const float* b_mom = (const float*)d_in[4];
    const float* atoms = (const float*)d_in[5];

    float* out = (float*)d_out;
    const int audio_elems = R_ROWS * SAMPLES;
    const int write_mom = (out_size >= audio_elems + R_ROWS * N_FRAMES) ? 1 : 0;
    float* out_mom = out + audio_elems;

    cudaFuncSetAttribute(k_gemm, cudaFuncAttributeMaxDynamicSharedMemorySize, GEMM_SMEM);

    k_hann<<<1, WIN>>>();
    k_tofp16<<<4096, 256>>>(atoms);
    k_sel_mom<<<R_ROWS, 256>>>(x, W_sel, b_sel, W_mom, b_mom, out_mom, write_mom);
    // grid.x = M tiles (8) fastest -> CTAs sharing an atoms N-strip run together (L2 reuse)
    k_gemm<<<dim3(R_ROWS / BM, SAMPLES / BN), 256, GEMM_SMEM>>>();
    k_epilogue<<<dim3(2, R_ROWS), 256>>>(out);
}

// round 17
// speedup vs baseline: 6.6857x; 1.3775x over previous
#include <cuda_runtime.h>
#include <cuda_fp16.h>
#include <math.h>
#include <stdint.h>

// Problem dims
#define R_ROWS   1024      // B*E = 16*64
#define LATENT   128
#define N_ATOMS  1024      // K of the big GEMM
#define N_FRAMES 128
#define SAMPLES  32768
#define WIN      512
#define HOP      256

#define RES_SCALE 16.0f        // res stored as fp16*16 (keeps values normal);
#define RES_INV   (1.0f/16.0f) // folded into sc[] in the epilogue
#define TWO_PI_OVER_WIN 0.01227184630308512983f   // 2*pi/512

// GEMM tiling: CTA 128x128, BK=64, 8 warps (warp tile 64x32), 2 CTAs/SM
#define BM 128
#define BN 128
#define BK 64
#define NT (N_ATOMS / BK)      // 16 k-tiles
#define A_ROWB 128
#define B_ROWB 256
#define OFF_A  0
#define A_B    (128 * A_ROWB)            // 16384
#define OFF_B  (A_B)
#define B_B    (BK * B_ROWB)             // 16384
#define STAGE_B (A_B + B_B)              // 32768
#define NSTAGE 3
#define GEMM_SMEM (NSTAGE * STAGE_B)     // 98304 per CTA

// Scratch (static device globals — no runtime allocation allowed)
__device__ __half g_selh[R_ROWS * N_ATOMS];     // 2 MB (fp16 softmax weights)
__device__ __half g_ath [N_ATOMS * SAMPLES];    // atoms fp16, [K][N] native  64 MB
__device__ __half g_resh[R_ROWS * SAMPLES];     // 64 MB (16*res, fp16)
__device__ float g_p1[R_ROWS * 2 * N_FRAMES];   // per-(row,block,half) hann1^2 partials
__device__ float g_p2[R_ROWS * 2 * N_FRAMES];   // hann2^2 partials
__device__ float g_mom[R_ROWS * N_FRAMES];

// ---------------------------------------------------------------------------
// low-level helpers (base-target sm_80+ instructions only)
// ---------------------------------------------------------------------------
__device__ __forceinline__ uint32_t smem_to_u32(const void* p) {
    uint32_t a;
    asm("{ .reg .u64 t; cvta.to.shared.u64 t, %1; cvt.u32.u64 %0, t; }" : "=r"(a) : "l"(p));
    return a;
}
#define CP_ASYNC16(dst, src) \
    asm volatile("cp.async.cg.shared.global [%0], [%1], 16;" :: "r"(dst), "l"(src))
#define CP_COMMIT()  asm volatile("cp.async.commit_group;" ::: "memory")
#define CP_WAIT1()   asm volatile("cp.async.wait_group 1;" ::: "memory")
#define CP_WAIT0()   asm volatile("cp.async.wait_group 0;" ::: "memory")

#define LDSM4(r, addr) \
    asm volatile("ldmatrix.sync.aligned.m8n8.x4.shared.b16 {%0,%1,%2,%3}, [%4];" \
        : "=r"((r)[0]), "=r"((r)[1]), "=r"((r)[2]), "=r"((r)[3]) : "r"(addr))
#define LDSM4T(r, addr) \
    asm volatile("ldmatrix.sync.aligned.m8n8.x4.trans.shared.b16 {%0,%1,%2,%3}, [%4];" \
        : "=r"((r)[0]), "=r"((r)[1]), "=r"((r)[2]), "=r"((r)[3]) : "r"(addr))

#define MMA_F16(c, a, b0, b1) \
    asm volatile("mma.sync.aligned.m16n8k16.row.col.f32.f16.f16.f32 " \
        "{%0,%1,%2,%3},{%4,%5,%6,%7},{%8,%9},{%0,%1,%2,%3};" \
        : "+f"((c)[0]), "+f"((c)[1]), "+f"((c)[2]), "+f"((c)[3]) \
        : "r"((a)[0]), "r"((a)[1]), "r"((a)[2]), "r"((a)[3]), "r"(b0), "r"(b1))

__device__ __forceinline__ float hann_at(int j) {
    return 0.5f * (1.0f - cosf(TWO_PI_OVER_WIN * (float)j));
}

// ---------------------------------------------------------------------------
// K_C: atoms f32 [K][S] -> fp16 [K][S] (pure streaming convert, no transpose)
// ---------------------------------------------------------------------------
__global__ __launch_bounds__(256) void k_tofp16(const float* __restrict__ atoms)
{
    const size_t total4 = (size_t)N_ATOMS * SAMPLES / 4;
    for (size_t i = (size_t)blockIdx.x * 256 + threadIdx.x; i < total4;
         i += (size_t)gridDim.x * 256) {
        float4 v = ((const float4*)atoms)[i];
        __half2 h0 = __floats2half2_rn(v.x, v.y);
        __half2 h1 = __floats2half2_rn(v.z, v.w);
        ((uint2*)g_ath)[i] = make_uint2(*(uint32_t*)&h0, *(uint32_t*)&h1);
    }
}

// ---------------------------------------------------------------------------
// K1: selection softmax (-> fp16) + momentum cumprod, 8 rows per block.
//     W_sel row loaded ONCE per block and reused across 8 rows (8x less L2).
// ---------------------------------------------------------------------------
#define SM_ROWS 8
__global__ __launch_bounds__(256) void k_sel_mom(
    const float* __restrict__ x,
    const float* __restrict__ W_sel, const float* __restrict__ b_sel,
    const float* __restrict__ W_mom, const float* __restrict__ b_mom,
    float* __restrict__ out_mom, int write_mom)
{
    __shared__ float xs[SM_ROWS][LATENT];          // 4 KB
    __shared__ float zt[SM_ROWS][N_ATOMS];         // 32 KB logits/exp scratch
    __shared__ float red[SM_ROWS][8];              // per-row warp partials
    __shared__ float rmax[SM_ROWS], rsum[SM_ROWS];
    __shared__ float lm[SM_ROWS][N_FRAMES];        // 4 KB

    const int r0  = blockIdx.x * SM_ROWS;
    const int tid = threadIdx.x;
    const int w   = tid >> 5;
    const int l   = tid & 31;

    // load 8 rows of x
    for (int i = tid; i < SM_ROWS * LATENT; i += 256)
        xs[i >> 7][i & 127] = x[r0 * LATENT + i];
    __syncthreads();

    // ---- selection logits: thread handles 4 atoms, 8 rows each ----
    #pragma unroll
    for (int i = 0; i < 4; i++) {
        const int a = tid + 256 * i;
        const float4* wp = (const float4*)(W_sel + a * LATENT);
        float acc[SM_ROWS];
        #pragma unroll
        for (int rr = 0; rr < SM_ROWS; rr++) acc[rr] = 0.f;
        #pragma unroll 8
        for (int l4 = 0; l4 < LATENT / 4; l4++) {
            float4 w4 = wp[l4];
            #pragma unroll
            for (int rr = 0; rr < SM_ROWS; rr++)
                acc[rr] += xs[rr][l4 * 4 + 0] * w4.x + xs[rr][l4 * 4 + 1] * w4.y
                         + xs[rr][l4 * 4 + 2] * w4.z + xs[rr][l4 * 4 + 3] * w4.w;
        }
        const float bb = b_sel[a];
        #pragma unroll
        for (int rr = 0; rr < SM_ROWS; rr++)
            zt[rr][a] = acc[rr] + bb;
    }
    __syncthreads();

    // ---- per-row max: warp w handles row w%8, strided over atoms ----
    {
        const int rr = w;                          // 8 warps -> 8 rows
        float m = -1e30f;
        for (int a = l; a < N_ATOMS; a += 32) m = fmaxf(m, zt[rr][a]);
        #pragma unroll
        for (int o = 16; o > 0; o >>= 1) m = fmaxf(m, __shfl_xor_sync(0xffffffffu, m, o));
        if (l == 0) rmax[rr] = m;
    }
    __syncthreads();

    // ---- exp + per-row sum ----
    {
        const int rr = w;
        const float m = rmax[rr];
        float s = 0.f;
        for (int a = l; a < N_ATOMS; a += 32) {
            const float e = expf(zt[rr][a] - m);
            zt[rr][a] = e;
            s += e;
        }
        #pragma unroll
        for (int o = 16; o > 0; o >>= 1) s += __shfl_xor_sync(0xffffffffu, s, o);
        if (l == 0) rsum[rr] = s;
    }
    __syncthreads();

    // ---- write fp16 sel (coalesced: tid over atoms, loop rows) ----
    #pragma unroll
    for (int rr = 0; rr < SM_ROWS; rr++) {
        const float inv = 1.0f / rsum[rr];
        #pragma unroll
        for (int i = 0; i < 4; i++) {
            const int a = tid + 256 * i;
            g_selh[(size_t)(r0 + rr) * N_ATOMS + a] = __float2half(zt[rr][a] * inv);
        }
    }

    // ---- momentum logits: thread = (frame = tid&127, rows 4*(tid>>7)..) ----
    {
        const int f  = tid & 127;
        const int rh = (tid >> 7) * 4;             // rows rh..rh+3
        const float4* wp = (const float4*)(W_mom + f * LATENT);
        float acc[4] = {0.f, 0.f, 0.f, 0.f};
        #pragma unroll 8
        for (int l4 = 0; l4 < LATENT / 4; l4++) {
            float4 w4 = wp[l4];
            #pragma unroll
            for (int rr = 0; rr < 4; rr++)
                acc[rr] += xs[rh + rr][l4 * 4 + 0] * w4.x + xs[rh + rr][l4 * 4 + 1] * w4.y
                         + xs[rh + rr][l4 * 4 + 2] * w4.z + xs[rh + rr][l4 * 4 + 3] * w4.w;
        }
        const float bb = b_mom[f];
        #pragma unroll
        for (int rr = 0; rr < 4; rr++) {
            const float sg = 1.0f / (1.0f + expf(-(acc[rr] + bb)));
            lm[rh + rr][f] = logf(1e-12f + 0.2f + 0.72f * sg);
        }
    }
    __syncthreads();
    if (tid < SM_ROWS) {
        float c = 0.f;
        const int r = r0 + tid;
        for (int f = 0; f < N_FRAMES; f++) {
            c += lm[tid][f];
            const float mm = expf(c);
            g_mom[r * N_FRAMES + f] = mm;
            if (write_mom) out_mom[r * N_FRAMES + f] = mm;
        }
    }
}

// ---------------------------------------------------------------------------
// K2: res = sel @ atoms, fp16 single-pass HMMA. BK=64, 1 barrier per 64-K.
//     Fused: per-(row,block) hann^2-weighted norm partials (exact f32).
//     res stored fp16 scaled by 16.  (unchanged from R14 except inline hann)
// ---------------------------------------------------------------------------
__global__ __launch_bounds__(256, 2) void k_gemm()
{
    extern __shared__ char sm_dyn[];
    __shared__ float hsq[WIN];
    __shared__ float s_part[4][BM][2];
    const uint32_t smem_u = smem_to_u32(sm_dyn);

    const int tid  = threadIdx.x;
    const int wid  = tid >> 5;
    const int lane = tid & 31;
    const int wm   = wid & 1;        // 2 warps in M  (64 rows)
    const int wn   = wid >> 1;       // 4 warps in N  (32 cols)
    const int mBase = blockIdx.x * BM;
    const int nBase = blockIdx.y * BN;

    {
        const float h0 = hann_at(tid);
        const float h1 = hann_at(tid + 256);
        hsq[tid] = h0 * h0;
        hsq[tid + 256] = h1 * h1;
    }

    // ---- per-thread gmem->smem copy descriptors (8 x 16B per stage) ----
    const __half* srcp[8];
    uint32_t dstoff[8];
    size_t   kstep[8];
    #pragma unroll
    for (int i = 0; i < 8; i++) {
        const int q = tid + i * 256;
        if (q < 1024) {
            const int row = q >> 3, c = q & 7;
            const int cs = c ^ (row & 7);
            srcp[i]   = g_selh + (size_t)(mBase + row) * N_ATOMS + c * 8;
            dstoff[i] = (uint32_t)(OFF_A + row * A_ROWB + cs * 16);
            kstep[i]  = BK;
        } else {
            const int qb = q - 1024;
            const int row = qb >> 4, c = qb & 15;
            const int cs = c ^ (row & 7);
            srcp[i]   = g_ath + (size_t)row * SAMPLES + nBase + c * 8;
            dstoff[i] = (uint32_t)(OFF_B + row * B_ROWB + cs * 16);
            kstep[i]  = (size_t)BK * SAMPLES;
        }
    }

    #define LOAD_STAGE(buf) do {                                        \
        const uint32_t sb_ = smem_u + (uint32_t)(buf) * STAGE_B;        \
        _Pragma("unroll")                                               \
        for (int i_ = 0; i_ < 8; i_++) {                                \
            CP_ASYNC16(sb_ + dstoff[i_], srcp[i_]);                     \
            srcp[i_] += kstep[i_];                                      \
        }                                                               \
        CP_COMMIT();                                                    \
    } while (0)

    const int a_lr = lane & 15;
    const int a_jb = lane >> 4;
    const int a_sw = a_lr & 7;
    const uint32_t a_rowoff = (uint32_t)(a_lr * A_ROWB);

    const int b_tile  = lane >> 3;
    const int b_kloc  = (b_tile & 1) * 8 + (lane & 7);
    const int b_ngrp  = b_tile >> 1;
    const uint32_t b_base = (uint32_t)(OFF_B + b_kloc * B_ROWB);
    const int b_cs0 = (wn * 4 + 0 * 2 + b_ngrp) ^ (b_kloc & 7);
    const int b_cs1 = (wn * 4 + 1 * 2 + b_ngrp) ^ (b_kloc & 7);

    float c[4][4][4];
    #pragma unroll
    for (int mi = 0; mi < 4; mi++)
        #pragma unroll
        for (int ni = 0; ni < 4; ni++)
            #pragma unroll
            for (int k = 0; k < 4; k++) c[mi][ni][k] = 0.f;

    LOAD_STAGE(0);
    LOAD_STAGE(1);

    for (int t = 0; t < NT; t++) {
        if (t == NT - 1) { CP_WAIT0(); } else { CP_WAIT1(); }
        __syncthreads();
        if (t + 2 < NT) LOAD_STAGE((t + 2) % NSTAGE);

        const uint32_t buf = smem_u + (uint32_t)(t % NSTAGE) * STAGE_B;

        #pragma unroll
        for (int ks = 0; ks < 4; ks++) {
            const uint32_t a_ch = (uint32_t)(((ks * 2 + a_jb) ^ a_sw) * 16);
            const uint32_t b_ko = (uint32_t)(ks * 16 * B_ROWB);

            uint32_t b0[4], b1[4];
            LDSM4T(b0, buf + b_base + b_ko + (uint32_t)(b_cs0 * 16));
            LDSM4T(b1, buf + b_base + b_ko + (uint32_t)(b_cs1 * 16));

            #pragma unroll
            for (int mi = 0; mi < 4; mi++) {
                uint32_t ah[4];
                const uint32_t a_addr = buf + (uint32_t)(OFF_A + (wm * 64 + mi * 16) * A_ROWB)
                                      + a_rowoff + a_ch;
                LDSM4(ah, a_addr);
                MMA_F16(c[mi][0], ah, b0[0], b0[1]);
                MMA_F16(c[mi][1], ah, b0[2], b0[3]);
                MMA_F16(c[mi][2], ah, b1[0], b1[1]);
                MMA_F16(c[mi][3], ah, b1[2], b1[3]);
            }
        }
    }

    // ---- epilogue 1: write 16*res as fp16 ----
    const int rbase = mBase + wm * 64 + (lane >> 2);
    const int cbase = nBase + wn * 32 + (lane & 3) * 2;
    #pragma unroll
    for (int mi = 0; mi < 4; mi++)
        #pragma unroll
        for (int ni = 0; ni < 4; ni++) {
            __half* p = g_resh + (size_t)(rbase + mi * 16) * SAMPLES + cbase + ni * 8;
            __half2 h0 = __floats2half2_rn(c[mi][ni][0] * RES_SCALE, c[mi][ni][1] * RES_SCALE);
            __half2 h1 = __floats2half2_rn(c[mi][ni][2] * RES_SCALE, c[mi][ni][3] * RES_SCALE);
            *(uint32_t*)p                 = *(uint32_t*)&h0;
            *(uint32_t*)(p + 8 * SAMPLES) = *(uint32_t*)&h1;
        }

    // ---- epilogue 2: hann^2-weighted norm partials (exact f32) ----
    const int jq = (nBase & 255) + wn * 32 + (lane & 3) * 2;
    #pragma unroll
    for (int mi = 0; mi < 4; mi++) {
        #pragma unroll
        for (int pr = 0; pr < 2; pr++) {
            float s1 = 0.f, s2 = 0.f;
            #pragma unroll
            for (int ni = 0; ni < 4; ni++) {
                #pragma unroll
                for (int e = 0; e < 2; e++) {
                    const float v = c[mi][ni][pr * 2 + e];
                    const int j = jq + ni * 8 + e;
                    s1 += v * v * hsq[j];
                    s2 += v * v * hsq[j + 256];
                }
            }
            s1 += __shfl_xor_sync(0xffffffffu, s1, 1);
            s1 += __shfl_xor_sync(0xffffffffu, s1, 2);
            s2 += __shfl_xor_sync(0xffffffffu, s2, 1);
            s2 += __shfl_xor_sync(0xffffffffu, s2, 2);
            if ((lane & 3) == 0) {
                const int rl = wm * 64 + mi * 16 + pr * 8 + (lane >> 2);
                s_part[wn][rl][0] = s1;
                s_part[wn][rl][1] = s2;
            }
        }
    }
    __syncthreads();
    if (tid < BM) {
        const float a1 = s_part[0][tid][0] + s_part[1][tid][0] + s_part[2][tid][0] + s_part[3][tid][0];
        const float a2 = s_part[0][tid][1] + s_part[1][tid][1] + s_part[2][tid][1] + s_part[3][tid][1];
        const int idx = (nBase >> 7);
        g_p1[(size_t)(mBase + tid) * 256 + idx] = a1;
        g_p2[(size_t)(mBase + tid) * 256 + idx] = a2;
    }
    #undef LOAD_STAGE
}

// ---------------------------------------------------------------------------
// K3: scales from partials + pointwise scale + overlap-add.
//     grid (2, R_ROWS): 2 blocks per row, each streams half the samples.
// ---------------------------------------------------------------------------
__global__ __launch_bounds__(256) void k_epilogue(float* __restrict__ out)
{
    __shared__ float hs[WIN];
    __shared__ float sc[N_FRAMES];
    const int r    = blockIdx.y;
    const int half = blockIdx.x;
    const int tid  = threadIdx.x;
    hs[tid] = hann_at(tid);
    hs[tid + 256] = hann_at(tid + 256);

    if (tid < N_FRAMES) {
        const float* p1 = g_p1 + (size_t)r * 256;
        const float* p2 = g_p2 + (size_t)r * 256;
        float n2 = p1[tid * 2] + p1[tid * 2 + 1];
        if (tid + 1 < N_FRAMES) n2 += p2[tid * 2 + 2] + p2[tid * 2 + 3];
        sc[tid] = g_mom[r * N_FRAMES + tid] / (sqrtf(n2) + 1e-8f) * RES_INV;
    }
    __syncthreads();

    const int sBeg = half * (SAMPLES / 2);
    for (int s0 = sBeg + tid * 4; s0 < sBeg + SAMPLES / 2; s0 += 1024) {
        const int f1 = s0 >> 8;
        const int j  = s0 & 255;
        const float g1 = sc[f1];
        const float g0 = (f1 > 0) ? sc[f1 - 1] : 0.f;
        uint2 rv = *(const uint2*)(g_resh + (size_t)r * SAMPLES + s0);
        float2 v0 = __half22float2(*(__half2*)&rv.x);
        float2 v1 = __half22float2(*(__half2*)&rv.y);
        float4 o;
        o.x = v0.x * (hs[j + 0] * g1 + hs[j + 0 + HOP] * g0);
        o.y = v0.y * (hs[j + 1] * g1 + hs[j + 1 + HOP] * g0);
        o.z = v1.x * (hs[j + 2] * g1 + hs[j + 2 + HOP] * g0);
        o.w = v1.y * (hs[j + 3] * g1 + hs[j + 3 + HOP] * g0);
        *(float4*)(out + (size_t)r * SAMPLES + s0) = o;
    }
}

// ---------------------------------------------------------------------------
extern "C" void kernel_launch(void* const* d_in, const int* in_sizes, int n_in,
                              void* d_out, int out_size)
{
    const float* x     = (const float*)d_in[0];
    const float* W_sel = (const float*)d_in[1];
    const float* b_sel = (const float*)d_in[2];
    const float* W_mom = (const float*)d_in[3];
    const float* b_mom = (const float*)d_in[4];
    const float* atoms = (const float*)d_in[5];

    float* out = (float*)d_out;
    const int audio_elems = R_ROWS * SAMPLES;
    const int write_mom = (out_size >= audio_elems + R_ROWS * N_FRAMES) ? 1 : 0;
    float* out_mom = out + audio_elems;

    cudaFuncSetAttribute(k_gemm, cudaFuncAttributeMaxDynamicSharedMemorySize, GEMM_SMEM);

    k_tofp16<<<4096, 256>>>(atoms);
    k_sel_mom<<<R_ROWS / SM_ROWS, 256>>>(x, W_sel, b_sel, W_mom, b_mom, out_mom, write_mom);
    // grid.x = M tiles (8) fastest -> CTAs sharing an atoms N-strip run together (L2 reuse)
    k_gemm<<<dim3(R_ROWS / BM, SAMPLES / BN), 256, GEMM_SMEM>>>();
    k_epilogue<<<dim3(2, R_ROWS), 256>>>(out);
}